// round 4
// baseline (speedup 1.0000x reference)
#include <cuda_runtime.h>
#include <math.h>

#define Nn 8192
#define Ee 131072
#define C0 64
#define C1 32
#define NSs 160     // 2*C0 + C1
#define NVv 128     // C0 + 2*C1
#define EPB 8       // edges per warp batch (edge kernel)
#define NPAIR 4     // EPB/2

typedef unsigned long long ull;

// ---------------- static device scratch ----------------
__device__ float g_s[Nn * C0];
__device__ float g_v[Nn * C1 * 3];
__device__ float g_skip_s[Nn * C0];
__device__ float g_skip_v[Nn * C1 * 3];
__device__ float g_agg_s[Nn * NSs];
__device__ float g_agg_v[Nn * NVv * 3];

__device__ __forceinline__ float silu_f(float x) {
    return __fdividef(x, 1.0f + __expf(-x));
}

// packed fp32x2 helpers (sm_100a): bit-exact dual fp32 FMA
__device__ __forceinline__ ull pack2(float x, float y) {
    ull r; asm("mov.b64 %0, {%1, %2};" : "=l"(r) : "f"(x), "f"(y)); return r;
}
__device__ __forceinline__ void unpack2(ull v, float& x, float& y) {
    asm("mov.b64 {%0, %1}, %2;" : "=f"(x), "=f"(y) : "l"(v));
}
__device__ __forceinline__ ull fma2(ull a, ull b, ull c) {
    ull d; asm("fma.rn.f32x2 %0, %1, %2, %3;" : "=l"(d) : "l"(a), "l"(b), "l"(c)); return d;
}
__device__ __forceinline__ ull dup2(float x) { return pack2(x, x); }
__device__ __forceinline__ ull lds64(const float* p) {
    return *(const ull*)p;
}

// ---------------- kernel 0: zero aggregation buffers ----------------
__global__ void zero_agg_kernel() {
    long i = (long)blockIdx.x * blockDim.x + threadIdx.x;
    long stride = (long)gridDim.x * blockDim.x;
    float4* a = (float4*)g_agg_s;
    long na = (long)Nn * NSs / 4;
    for (long j = i; j < na; j += stride) a[j] = make_float4(0.f, 0.f, 0.f, 0.f);
    float4* b = (float4*)g_agg_v;
    long nb = (long)Nn * NVv * 3 / 4;
    for (long j = i; j < nb; j += stride) b[j] = make_float4(0.f, 0.f, 0.f, 0.f);
}

// ---------------- kernel 1: node pre (Wu0/Wu1 + skips) ----------------
__global__ void __launch_bounds__(256) node_pre_kernel(
    const float* __restrict__ s_in, const float* __restrict__ v_in,
    const int* __restrict__ species,
    const float* __restrict__ Wskip0, const float* __restrict__ Wskip1,
    const float* __restrict__ Wu0, const float* __restrict__ Wu1)
{
    extern __shared__ float sm[];
    float* sWu0 = sm;                  // 4096
    float* sWu1 = sWu0 + 4096;         // 1024
    float* sWs0 = sWu1 + 1024;         // 16384
    float* sWs1 = sWs0 + 16384;        // 4096
    float* bufs = sWs1 + 4096;         // 8 warps * 160

    int tid = threadIdx.x;
    for (int i = tid; i < 4096;  i += blockDim.x) sWu0[i] = Wu0[i];
    for (int i = tid; i < 1024;  i += blockDim.x) sWu1[i] = Wu1[i];
    for (int i = tid; i < 16384; i += blockDim.x) sWs0[i] = Wskip0[i];
    for (int i = tid; i < 4096;  i += blockDim.x) sWs1[i] = Wskip1[i];
    __syncthreads();

    int w = tid >> 5, lane = tid & 31;
    float* sb = bufs + w * 160;
    float* vb = sb + 64;
    int warpsTotal = gridDim.x * 8;

    for (int n = blockIdx.x * 8 + w; n < Nn; n += warpsTotal) {
        sb[lane]      = s_in[n * 64 + lane];
        sb[lane + 32] = s_in[n * 64 + lane + 32];
        vb[lane]      = v_in[n * 96 + lane];
        vb[lane + 32] = v_in[n * 96 + lane + 32];
        vb[lane + 64] = v_in[n * 96 + lane + 64];
        __syncwarp();
        int sp = species[n];
        const float* Ws0 = sWs0 + sp * 4096;
        const float* Ws1 = sWs1 + sp * 1024;

        float a0 = 0.f, a1 = 0.f, b0 = 0.f, b1 = 0.f;
        #pragma unroll 8
        for (int c = 0; c < 64; c++) {
            float x = sb[c];
            a0 = fmaf(x, sWu0[c * 64 + lane],      a0);
            a1 = fmaf(x, sWu0[c * 64 + lane + 32], a1);
            b0 = fmaf(x, Ws0[c * 64 + lane],       b0);
            b1 = fmaf(x, Ws0[c * 64 + lane + 32],  b1);
        }
        g_s[n * 64 + lane]      = a0;
        g_s[n * 64 + lane + 32] = a1;
        g_skip_s[n * 64 + lane]      = b0;
        g_skip_s[n * 64 + lane + 32] = b1;

        float u0 = 0.f, u1 = 0.f, u2 = 0.f, k0 = 0.f, k1 = 0.f, k2 = 0.f;
        #pragma unroll 8
        for (int c = 0; c < 32; c++) {
            float wu = sWu1[c * 32 + lane];
            float wk = Ws1[c * 32 + lane];
            float x0 = vb[c * 3], x1 = vb[c * 3 + 1], x2 = vb[c * 3 + 2];
            u0 = fmaf(x0, wu, u0); u1 = fmaf(x1, wu, u1); u2 = fmaf(x2, wu, u2);
            k0 = fmaf(x0, wk, k0); k1 = fmaf(x1, wk, k1); k2 = fmaf(x2, wk, k2);
        }
        g_v[n * 96 + lane * 3]     = u0;
        g_v[n * 96 + lane * 3 + 1] = u1;
        g_v[n * 96 + lane * 3 + 2] = u2;
        g_skip_v[n * 96 + lane * 3]     = k0;
        g_skip_v[n * 96 + lane * 3 + 1] = k1;
        g_skip_v[n * 96 + lane * 3 + 2] = k2;
        __syncwarp();
    }
}

// ---------------- kernel 2: fused edge MLP (fp32x2 packed) + scatter ----------------
__global__ void __launch_bounds__(384) edge_kernel(
    const float* __restrict__ radial, const float* __restrict__ Y0,
    const float* __restrict__ Y1,
    const int* __restrict__ senders, const int* __restrict__ receivers,
    const float* __restrict__ Wm1, const float* __restrict__ Wm2,
    const float* __restrict__ Wm3)
{
    extern __shared__ float sm[];
    float* sWm1 = sm;                 // 512
    float* sWm2 = sWm1 + 512;         // 4096
    float* sWm3 = sWm2 + 4096;        // 18432
    float* wb   = sWm3 + 18432;

    int tid = threadIdx.x, w = tid >> 5, lane = tid & 31;
    for (int i = tid; i < 512;   i += blockDim.x) sWm1[i] = Wm1[i];
    for (int i = tid; i < 4096;  i += blockDim.x) sWm2[i] = Wm2[i];
    for (int i = tid; i < 18432; i += blockDim.x) sWm3[i] = Wm3[i];
    __syncthreads();

    const int perW = 512 + 512 + 544;   // h1(pairs) + h2(pairs) + msg
    float* h1f = wb + w * perW;
    float* h2f = h1f + 512;
    float* msg = h2f + 512;
    ull* h1u = (ull*)h1f;
    ull* h2u = (ull*)h2f;

    int nwarps = gridDim.x * 12;
    int gw = blockIdx.x * 12 + w;
    const float inv_s3 = 0.57735026918962576f;

    for (int e0 = gw * EPB; e0 < Ee; e0 += nwarps * EPB) {
        // ---- layer 1 ----
        #pragma unroll
        for (int p = 0; p < NPAIR; p++) {
            float sv[2][2];
            #pragma unroll
            for (int hh = 0; hh < 2; hh++) {
                int e = e0 + 2 * p + hh;
                float rv = (lane < 8) ? radial[e * 8 + lane] : 0.f;
                float a0 = 0.f, a1 = 0.f;
                #pragma unroll
                for (int k = 0; k < 8; k++) {
                    float rk = __shfl_sync(0xffffffffu, rv, k);
                    a0 = fmaf(rk, sWm1[k * 64 + lane],      a0);
                    a1 = fmaf(rk, sWm1[k * 64 + lane + 32], a1);
                }
                sv[hh][0] = silu_f(a0);
                sv[hh][1] = silu_f(a1);
            }
            h1u[p * 64 + lane]      = pack2(sv[0][0], sv[1][0]);
            h1u[p * 64 + lane + 32] = pack2(sv[0][1], sv[1][1]);
        }
        __syncwarp();

        // ---- layer 2 ----
        {
            ull acc0[NPAIR], acc1[NPAIR];
            #pragma unroll
            for (int p = 0; p < NPAIR; p++) { acc0[p] = 0ull; acc1[p] = 0ull; }
            for (int k = 0; k < 64; k++) {
                float w0 = sWm2[k * 64 + lane];
                float w1 = sWm2[k * 64 + lane + 32];
                ull w0p = dup2(w0);
                ull w1p = dup2(w1);
                #pragma unroll
                for (int p = 0; p < NPAIR; p++) {
                    ull hp = h1u[p * 64 + k];
                    acc0[p] = fma2(hp, w0p, acc0[p]);
                    acc1[p] = fma2(hp, w1p, acc1[p]);
                }
            }
            #pragma unroll
            for (int p = 0; p < NPAIR; p++) {
                float x, y;
                unpack2(acc0[p], x, y);
                h2u[p * 64 + lane] = pack2(silu_f(x), silu_f(y));
                unpack2(acc1[p], x, y);
                h2u[p * 64 + lane + 32] = pack2(silu_f(x), silu_f(y));
            }
        }
        __syncwarp();

        // ---- layer 3 ----
        ull m2[NPAIR * 9];
        #pragma unroll
        for (int i = 0; i < NPAIR * 9; i++) m2[i] = 0ull;

        for (int k = 0; k < 64; k++) {
            ull hp[NPAIR];
            #pragma unroll
            for (int p = 0; p < NPAIR; p++) hp[p] = h2u[p * 64 + k];
            #pragma unroll
            for (int r = 0; r < 9; r++) {
                float wv = sWm3[k * 288 + lane + 32 * r];
                ull wp = dup2(wv);
                #pragma unroll
                for (int p = 0; p < NPAIR; p++)
                    m2[p * 9 + r] = fma2(hp[p], wp, m2[p * 9 + r]);
            }
        }

        // ---- messages + scatter ----
        #pragma unroll
        for (int t = 0; t < EPB; t++) {
            int pp = t >> 1, hh = t & 1;
            float mr[9];
            #pragma unroll
            for (int r = 0; r < 9; r++) {
                float lo, hi;
                unpack2(m2[pp * 9 + r], lo, hi);
                mr[r] = hh ? hi : lo;
            }
            int e = e0 + t;
            int snd = senders[e];
            int rcv = receivers[e];
            float m0  = g_s[snd * 64 + lane];
            float m1  = g_s[snd * 64 + lane + 32];
            float mv0 = g_v[snd * 96 + lane * 3];
            float mv1 = g_v[snd * 96 + lane * 3 + 1];
            float mv2 = g_v[snd * 96 + lane * 3 + 2];
            float y0  = Y0[e];
            float y10 = Y1[e * 3], y11 = Y1[e * 3 + 1], y12 = Y1[e * 3 + 2];
            float dot = (mv0 * y10 + mv1 * y11 + mv2 * y12) * inv_s3;

            msg[lane]       = m0 * mr[0];
            msg[32 + lane]  = m1 * mr[1];
            msg[64 + lane]  = m0 * y0 * mr[2];
            msg[96 + lane]  = m1 * y0 * mr[3];
            msg[128 + lane] = dot * mr[4];
            int b0 = 160 + lane * 3;
            msg[b0]     = mv0 * mr[5];
            msg[b0 + 1] = mv1 * mr[5];
            msg[b0 + 2] = mv2 * mr[5];
            int b1 = 160 + (32 + lane) * 3;
            float f6 = m0 * mr[6];
            msg[b1]     = f6 * y10;
            msg[b1 + 1] = f6 * y11;
            msg[b1 + 2] = f6 * y12;
            int b2 = 160 + (64 + lane) * 3;
            float f7 = m1 * mr[7];
            msg[b2]     = f7 * y10;
            msg[b2 + 1] = f7 * y11;
            msg[b2 + 2] = f7 * y12;
            int b3 = 160 + (96 + lane) * 3;
            float f8 = y0 * mr[8];
            msg[b3]     = mv0 * f8;
            msg[b3 + 1] = mv1 * f8;
            msg[b3 + 2] = mv2 * f8;
            __syncwarp();

            float* aggs = g_agg_s + (long)rcv * NSs;
            float* aggv = g_agg_v + (long)rcv * (NVv * 3);
            const float4* m4 = (const float4*)msg;
            #pragma unroll
            for (int gi = 0; gi < 5; gi++) {
                int g = lane + gi * 32;
                if (g < 136) {
                    float4 vv = m4[g];
                    float* p = (g < 40) ? (aggs + 4 * g) : (aggv + 4 * (g - 40));
                    asm volatile("red.global.add.v4.f32 [%0], {%1, %2, %3, %4};"
                                 :: "l"(p), "f"(vv.x), "f"(vv.y), "f"(vv.z), "f"(vv.w)
                                 : "memory");
                }
            }
            __syncwarp();
        }
    }
}

// ---------------- kernel 3: node post, fp32x2-packed GEMVs, 768 threads ----------------
// per-warp scratch layout (floats, 808 total):
//   [0:64)    srow   (s1, later s_final)           persistent
//   [64:160)  vx/vy/vz (32 each)                   persistent
//   [160:168) frow                                  persistent
//   phase A:  [168:328) asr      [328:712) av3 (SoA xyz, 128 each)
//   phase B:  [168:424) fs       [424:808) u (SoA xyz, 128 each)
#define PW 808
__global__ void __launch_bounds__(768) node_post_kernel(
    const float* __restrict__ x_node,
    const float* __restrict__ Wd0, const float* __restrict__ Wd1,
    const float* __restrict__ Wt0, const float* __restrict__ Wt1,
    const float* __restrict__ Wq,  const float* __restrict__ wqml,
    const float* __restrict__ Wo,  const float* __restrict__ bo,
    float* __restrict__ out0, float* __restrict__ outS, float* __restrict__ outV)
{
    extern __shared__ float sm[];
    float* sWd0  = sm;                   // 10240  [c*64 + d]
    float* sWd1T = sWd0 + 10240;         // 32*130 = 4160  [d*130 + c]
    float* sWt0  = sWd1T + 4160;         // 16384  [k*64 + d]
    float* sWt1T = sWt0 + 16384;         // 32*130 = 4160  [d*130 + k]
    float* sWq   = sWt1T + 4160;         // 512
    float* cw    = sWq + 512;            // 24
    float* sw_   = cw + 24;              // 24
    float* sWo   = sw_ + 24;             // 8
    float* bufs  = sWo + 8;              // 24 warps * PW

    int tid = threadIdx.x;
    for (int i = tid; i < 10240; i += blockDim.x) sWd0[i] = Wd0[i];
    for (int i = tid; i < 4096;  i += blockDim.x) {
        int c = i >> 5, d = i & 31;
        sWd1T[d * 130 + c] = Wd1[i];
        sWt1T[d * 130 + c] = Wt1[i];
    }
    for (int i = tid; i < 16384; i += blockDim.x) sWt0[i] = Wt0[i];
    for (int i = tid; i < 512;   i += blockDim.x) sWq[i]  = Wq[i];
    if (tid < 24) {
        float ang = 0.5f * wqml[tid];
        cw[tid]  = cosf(ang);
        sw_[tid] = sinf(ang);
    }
    if (tid < 8) sWo[tid] = Wo[tid];
    __syncthreads();

    int w = tid >> 5, lane = tid & 31;
    float* base = bufs + w * PW;
    float* srow = base;            // 64
    float* vx   = base + 64;       // 32
    float* vy   = base + 96;       // 32
    float* vz   = base + 128;      // 32
    float* frow = base + 160;      // 8
    float* asr  = base + 168;      // 160 (phase A)
    float* av3  = base + 328;      // 384 (phase A) [comp*128 + c]
    float* fs   = base + 168;      // 256 (phase B)
    float* usoa = base + 424;      // 384 (phase B) [comp*128 + k]

    const float inv16 = 1.0f / 16.0f;
    float bo0 = bo[0];
    int warpsTotal = gridDim.x * 24;

    for (int n = blockIdx.x * 24 + w; n < Nn; n += warpsTotal) {
        // ---- stage agg rows ----
        #pragma unroll
        for (int i = 0; i < 5; i++)  asr[lane + 32 * i] = g_agg_s[(long)n * 160 + lane + 32 * i];
        #pragma unroll
        for (int i = 0; i < 12; i++) {
            int idx = lane + 32 * i;
            float val = g_agg_v[(long)n * 384 + idx];
            int c = idx / 3, comp = idx - 3 * c;
            av3[comp * 128 + c] = val;
        }
        __syncwarp();

        // ---- s1 = agg_s @ Wd0 / 16 : lane owns cols (2lane, 2lane+1) ----
        {
            ull acc = 0ull;
            #pragma unroll 4
            for (int cp = 0; cp < 80; cp++) {
                ull xp = lds64(asr + 2 * cp);
                float x0, x1; unpack2(xp, x0, x1);
                ull w0 = lds64(sWd0 + (2 * cp) * 64 + 2 * lane);
                ull w1 = lds64(sWd0 + (2 * cp + 1) * 64 + 2 * lane);
                acc = fma2(w0, dup2(x0), acc);
                acc = fma2(w1, dup2(x1), acc);
            }
            float a, b; unpack2(acc, a, b);
            srow[2 * lane]     = a * inv16;
            srow[2 * lane + 1] = b * inv16;
        }

        // ---- v1 = agg_v @ Wd1 / 16 : lane owns col lane, packed over k-pairs ----
        {
            ull ax = 0ull, ay = 0ull, az = 0ull;
            const float* wt = sWd1T + lane * 130;
            #pragma unroll 4
            for (int cp = 0; cp < 64; cp++) {
                ull wp = lds64(wt + 2 * cp);
                ax = fma2(wp, lds64(av3 + 2 * cp),       ax);
                ay = fma2(wp, lds64(av3 + 128 + 2 * cp), ay);
                az = fma2(wp, lds64(av3 + 256 + 2 * cp), az);
            }
            float lo, hi;
            unpack2(ax, lo, hi); vx[lane] = (lo + hi) * inv16;
            unpack2(ay, lo, hi); vy[lane] = (lo + hi) * inv16;
            unpack2(az, lo, hi); vz[lane] = (lo + hi) * inv16;
        }
        __syncwarp();

        float xv[4];
        #pragma unroll
        for (int a = 0; a < 4; a++) xv[a] = x_node[n * 4 + a];

        // ---- stage fs[a*64+c] = xa * s1[c], u[comp][a*32+c] = xa * v1[comp][c] ----
        {
            #pragma unroll
            for (int j = 0; j < 8; j++) {
                int i = lane + 32 * j;
                fs[i] = xv[i >> 6] * srow[i & 63];
            }
            float vxl = vx[lane], vyl = vy[lane], vzl = vz[lane];
            #pragma unroll
            for (int j = 0; j < 4; j++) {
                float xa = xv[j];
                usoa[j * 32 + lane]       = xa * vxl;
                usoa[128 + j * 32 + lane] = xa * vyl;
                usoa[256 + j * 32 + lane] = xa * vzl;
            }
        }
        __syncwarp();

        // ---- s2 = fs @ Wt0 : lane owns cols (2lane, 2lane+1) ----
        float sf0, sf1;
        {
            ull acc = 0ull;
            #pragma unroll 4
            for (int kp = 0; kp < 128; kp++) {
                ull fp = lds64(fs + 2 * kp);
                float f0, f1; unpack2(fp, f0, f1);
                ull w0 = lds64(sWt0 + (2 * kp) * 64 + 2 * lane);
                ull w1 = lds64(sWt0 + (2 * kp + 1) * 64 + 2 * lane);
                acc = fma2(w0, dup2(f0), acc);
                acc = fma2(w1, dup2(f1), acc);
            }
            float a, b; unpack2(acc, a, b);
            // skip add (float2 aligned)
            ull sk = *(const ull*)(g_skip_s + n * 64 + 2 * lane);
            float k0, k1; unpack2(sk, k0, k1);
            sf0 = a + k0; sf1 = b + k1;
            *(ull*)(outS + n * 64 + 2 * lane) = pack2(sf0, sf1);
        }

        // ---- v2 = u @ Wt1 : lane owns col lane, packed k-pairs ----
        {
            ull ax = 0ull, ay = 0ull, az = 0ull;
            const float* wt = sWt1T + lane * 130;
            #pragma unroll 4
            for (int kp = 0; kp < 64; kp++) {
                ull wp = lds64(wt + 2 * kp);
                ax = fma2(wp, lds64(usoa + 2 * kp),       ax);
                ay = fma2(wp, lds64(usoa + 128 + 2 * kp), ay);
                az = fma2(wp, lds64(usoa + 256 + 2 * kp), az);
            }
            float lo, hi;
            unpack2(ax, lo, hi); float p0 = lo + hi;
            unpack2(ay, lo, hi); float p1 = lo + hi;
            unpack2(az, lo, hi); float p2 = lo + hi;
            outV[n * 96 + lane * 3]     = p0 + g_skip_v[n * 96 + lane * 3];
            outV[n * 96 + lane * 3 + 1] = p1 + g_skip_v[n * 96 + lane * 3 + 1];
            outV[n * 96 + lane * 3 + 2] = p2 + g_skip_v[n * 96 + lane * 3 + 2];
        }

        // ---- feats = s_final @ Wq ----
        __syncwarp();
        srow[2 * lane] = sf0; srow[2 * lane + 1] = sf1;
        __syncwarp();
        if (lane < 8) {
            float f = 0.f;
            #pragma unroll 8
            for (int c = 0; c < 64; c++) f = fmaf(srow[c], sWq[c * 8 + lane], f);
            frow[lane] = f;
        }
        __syncwarp();

        // ---- quantum circuit: idx = lane*8 + l; qubit q <-> idx bit (7-q) ----
        float cs[8], sn[8];
        #pragma unroll
        for (int q = 0; q < 8; q++) {
            float a = 0.5f * frow[q];
            __sincosf(a, &sn[q], &cs[q]);
        }
        float lf = 1.f;
        #pragma unroll
        for (int j = 0; j < 5; j++) {
            int q = 4 - j;
            lf *= ((lane >> j) & 1) ? sn[q] : cs[q];
        }
        float amp[8];
        #pragma unroll
        for (int l = 0; l < 8; l++) {
            float f = lf;
            f *= (l & 4) ? sn[5] : cs[5];
            f *= (l & 2) ? sn[6] : cs[6];
            f *= (l & 1) ? sn[7] : cs[7];
            amp[l] = f;
        }

        #pragma unroll
        for (int L = 0; L < 3; L++) {
            #pragma unroll
            for (int q = 0; q < 8; q++) {
                float c = cw[L * 8 + q], s = sw_[L * 8 + q];
                const int b = 7 - q;
                if (b >= 3) {
                    const int m = 1 << (b - 3);
                    int bit = (lane >> (b - 3)) & 1;
                    #pragma unroll
                    for (int l = 0; l < 8; l++) {
                        float p = __shfl_xor_sync(0xffffffffu, amp[l], m);
                        amp[l] = bit ? fmaf(s, p, c * amp[l]) : (c * amp[l] - s * p);
                    }
                } else {
                    const int tm = 1 << b;
                    #pragma unroll
                    for (int l = 0; l < 8; l++) {
                        if (!(l & tm)) {
                            float a0 = amp[l], a1 = amp[l | tm];
                            amp[l]      = c * a0 - s * a1;
                            amp[l | tm] = fmaf(s, a0, c * a1);
                        }
                    }
                }
            }
            #pragma unroll
            for (int q = 0; q < 8; q++) {
                const int bc = 7 - q;
                const int bt = 7 - ((q + 1) & 7);
                if (bt >= 3) {
                    const int m = 1 << (bt - 3);
                    #pragma unroll
                    for (int l = 0; l < 8; l++) {
                        float p = __shfl_xor_sync(0xffffffffu, amp[l], m);
                        int ctrl = (bc >= 3) ? ((lane >> (bc - 3)) & 1) : ((l >> bc) & 1);
                        amp[l] = ctrl ? p : amp[l];
                    }
                } else {
                    const int tm = 1 << bt;
                    if (bc >= 3) {
                        int ctrl = (lane >> (bc - 3)) & 1;
                        #pragma unroll
                        for (int l = 0; l < 8; l++) {
                            if (!(l & tm)) {
                                float a = amp[l], bb = amp[l | tm];
                                amp[l]      = ctrl ? bb : a;
                                amp[l | tm] = ctrl ? a : bb;
                            }
                        }
                    } else {
                        #pragma unroll
                        for (int l = 0; l < 8; l++) {
                            if (!(l & tm) && ((l >> bc) & 1)) {
                                float tmp = amp[l];
                                amp[l] = amp[l | tm];
                                amp[l | tm] = tmp;
                            }
                        }
                    }
                }
            }
        }

        float tsum = 0.f, tb0 = 0.f, tb1 = 0.f, tb2 = 0.f;
        #pragma unroll
        for (int l = 0; l < 8; l++) {
            float p = amp[l] * amp[l];
            tsum += p;
            tb0 += (l & 1) ? -p : p;
            tb1 += (l & 2) ? -p : p;
            tb2 += (l & 4) ? -p : p;
        }
        float lanesum = 0.f;
        #pragma unroll
        for (int q = 0; q < 5; q++) {
            float sgn = ((lane >> (4 - q)) & 1) ? -1.f : 1.f;
            lanesum = fmaf(sgn * sWo[q], 1.f, lanesum);
        }
        float op = sWo[7] * tb0 + sWo[6] * tb1 + sWo[5] * tb2 + tsum * lanesum;
        #pragma unroll
        for (int o = 16; o > 0; o >>= 1)
            op += __shfl_xor_sync(0xffffffffu, op, o);
        if (lane == 0) out0[n] = op + bo0;
        __syncwarp();
    }
}

// ---------------- launch ----------------
extern "C" void kernel_launch(void* const* d_in, const int* in_sizes, int n_in,
                              void* d_out, int out_size) {
    const float* s_in     = (const float*)d_in[0];
    const float* v_in     = (const float*)d_in[1];
    const float* x_node   = (const float*)d_in[2];
    const float* radial   = (const float*)d_in[3];
    const float* Y0       = (const float*)d_in[4];
    const float* Y1       = (const float*)d_in[5];
    const int*   species  = (const int*)d_in[6];
    const int*   senders  = (const int*)d_in[7];
    const int*   receivers= (const int*)d_in[8];
    const float* Wskip0   = (const float*)d_in[9];
    const float* Wskip1   = (const float*)d_in[10];
    const float* Wu0      = (const float*)d_in[11];
    const float* Wu1      = (const float*)d_in[12];
    const float* Wm1      = (const float*)d_in[13];
    const float* Wm2      = (const float*)d_in[14];
    const float* Wm3      = (const float*)d_in[15];
    const float* Wd0      = (const float*)d_in[16];
    const float* Wd1      = (const float*)d_in[17];
    const float* Wt0      = (const float*)d_in[18];
    const float* Wt1      = (const float*)d_in[19];
    const float* Wq       = (const float*)d_in[20];
    const float* wqml     = (const float*)d_in[21];
    const float* Wo       = (const float*)d_in[22];
    const float* bo       = (const float*)d_in[23];

    float* out0 = (float*)d_out;
    float* outS = out0 + Nn;
    float* outV = outS + Nn * C0;

    static bool attr_done = false;
    size_t smem_pre  = (4096 + 1024 + 16384 + 4096 + 8 * 160) * sizeof(float);
    size_t smem_edge = (512 + 4096 + 18432 + 12 * (512 + 512 + 544)) * sizeof(float);
    size_t smem_post = (10240 + 4160 + 16384 + 4160 + 512 + 24 + 24 + 8 + 24 * PW) * sizeof(float);
    if (!attr_done) {
        cudaFuncSetAttribute(node_pre_kernel,  cudaFuncAttributeMaxDynamicSharedMemorySize, (int)smem_pre);
        cudaFuncSetAttribute(edge_kernel,      cudaFuncAttributeMaxDynamicSharedMemorySize, (int)smem_edge);
        cudaFuncSetAttribute(node_post_kernel, cudaFuncAttributeMaxDynamicSharedMemorySize, (int)smem_post);
        attr_done = true;
    }

    zero_agg_kernel<<<1024, 256>>>();
    node_pre_kernel<<<296, 256, smem_pre>>>(s_in, v_in, species, Wskip0, Wskip1, Wu0, Wu1);
    edge_kernel<<<148, 384, smem_edge>>>(radial, Y0, Y1, senders, receivers, Wm1, Wm2, Wm3);
    node_post_kernel<<<148, 768, smem_post>>>(x_node, Wd0, Wd1, Wt0, Wt1, Wq, wqml, Wo, bo,
                                              out0, outS, outV);
}

// round 5
// speedup vs baseline: 1.0138x; 1.0138x over previous
#include <cuda_runtime.h>
#include <math.h>

#define Nn 8192
#define Ee 131072
#define C0 64
#define C1 32
#define NSs 160     // 2*C0 + C1
#define NVv 128     // C0 + 2*C1
#define EPB 8       // edges per warp batch (edge kernel)
#define NPAIR 4     // EPB/2

typedef unsigned long long ull;

// ---------------- static device scratch ----------------
__device__ float g_s[Nn * C0];
__device__ float g_v[Nn * C1 * 3];
__device__ float g_skip_s[Nn * C0];
__device__ float g_skip_v[Nn * C1 * 3];
__device__ float g_agg_s[Nn * NSs];
__device__ float g_agg_v[Nn * NVv * 3];
__device__ float g_s1[Nn * C0];          // s after Wd0
__device__ float g_v1[Nn * 3 * C1];      // v after Wd1, rows (n,i)
__device__ float g_ts[Nn * 4 * C0];      // expanded scalar, [n, a*64+c]
__device__ float g_tv[Nn * 3 * 4 * C1];  // expanded vector, [(3n+i), a*32+c]

__device__ __forceinline__ float silu_f(float x) {
    return __fdividef(x, 1.0f + __expf(-x));
}

// packed fp32x2 helpers (sm_100a): bit-exact dual fp32 FMA
__device__ __forceinline__ ull pack2(float x, float y) {
    ull r; asm("mov.b64 %0, {%1, %2};" : "=l"(r) : "f"(x), "f"(y)); return r;
}
__device__ __forceinline__ void unpack2(ull v, float& x, float& y) {
    asm("mov.b64 {%0, %1}, %2;" : "=f"(x), "=f"(y) : "l"(v));
}
__device__ __forceinline__ ull fma2(ull a, ull b, ull c) {
    ull d; asm("fma.rn.f32x2 %0, %1, %2, %3;" : "=l"(d) : "l"(a), "l"(b), "l"(c)); return d;
}
__device__ __forceinline__ ull dup2(float x) { return pack2(x, x); }
__device__ __forceinline__ ull lds64(const float* p) { return *(const ull*)p; }

// ---------------- kernel 0: zero aggregation buffers ----------------
__global__ void zero_agg_kernel() {
    long i = (long)blockIdx.x * blockDim.x + threadIdx.x;
    long stride = (long)gridDim.x * blockDim.x;
    float4* a = (float4*)g_agg_s;
    long na = (long)Nn * NSs / 4;
    for (long j = i; j < na; j += stride) a[j] = make_float4(0.f, 0.f, 0.f, 0.f);
    float4* b = (float4*)g_agg_v;
    long nb = (long)Nn * NVv * 3 / 4;
    for (long j = i; j < nb; j += stride) b[j] = make_float4(0.f, 0.f, 0.f, 0.f);
}

// ---------------- kernel 1: node pre (Wu0/Wu1 + skips) ----------------
__global__ void __launch_bounds__(256) node_pre_kernel(
    const float* __restrict__ s_in, const float* __restrict__ v_in,
    const int* __restrict__ species,
    const float* __restrict__ Wskip0, const float* __restrict__ Wskip1,
    const float* __restrict__ Wu0, const float* __restrict__ Wu1)
{
    extern __shared__ float sm[];
    float* sWu0 = sm;                  // 4096
    float* sWu1 = sWu0 + 4096;         // 1024
    float* sWs0 = sWu1 + 1024;         // 16384
    float* sWs1 = sWs0 + 16384;        // 4096
    float* bufs = sWs1 + 4096;         // 8 warps * 160

    int tid = threadIdx.x;
    for (int i = tid; i < 4096;  i += blockDim.x) sWu0[i] = Wu0[i];
    for (int i = tid; i < 1024;  i += blockDim.x) sWu1[i] = Wu1[i];
    for (int i = tid; i < 16384; i += blockDim.x) sWs0[i] = Wskip0[i];
    for (int i = tid; i < 4096;  i += blockDim.x) sWs1[i] = Wskip1[i];
    __syncthreads();

    int w = tid >> 5, lane = tid & 31;
    float* sb = bufs + w * 160;
    float* vb = sb + 64;
    int warpsTotal = gridDim.x * 8;

    for (int n = blockIdx.x * 8 + w; n < Nn; n += warpsTotal) {
        sb[lane]      = s_in[n * 64 + lane];
        sb[lane + 32] = s_in[n * 64 + lane + 32];
        vb[lane]      = v_in[n * 96 + lane];
        vb[lane + 32] = v_in[n * 96 + lane + 32];
        vb[lane + 64] = v_in[n * 96 + lane + 64];
        __syncwarp();
        int sp = species[n];
        const float* Ws0 = sWs0 + sp * 4096;
        const float* Ws1 = sWs1 + sp * 1024;

        float a0 = 0.f, a1 = 0.f, b0 = 0.f, b1 = 0.f;
        #pragma unroll 8
        for (int c = 0; c < 64; c++) {
            float x = sb[c];
            a0 = fmaf(x, sWu0[c * 64 + lane],      a0);
            a1 = fmaf(x, sWu0[c * 64 + lane + 32], a1);
            b0 = fmaf(x, Ws0[c * 64 + lane],       b0);
            b1 = fmaf(x, Ws0[c * 64 + lane + 32],  b1);
        }
        g_s[n * 64 + lane]      = a0;
        g_s[n * 64 + lane + 32] = a1;
        g_skip_s[n * 64 + lane]      = b0;
        g_skip_s[n * 64 + lane + 32] = b1;

        float u0 = 0.f, u1 = 0.f, u2 = 0.f, k0 = 0.f, k1 = 0.f, k2 = 0.f;
        #pragma unroll 8
        for (int c = 0; c < 32; c++) {
            float wu = sWu1[c * 32 + lane];
            float wk = Ws1[c * 32 + lane];
            float x0 = vb[c * 3], x1 = vb[c * 3 + 1], x2 = vb[c * 3 + 2];
            u0 = fmaf(x0, wu, u0); u1 = fmaf(x1, wu, u1); u2 = fmaf(x2, wu, u2);
            k0 = fmaf(x0, wk, k0); k1 = fmaf(x1, wk, k1); k2 = fmaf(x2, wk, k2);
        }
        g_v[n * 96 + lane * 3]     = u0;
        g_v[n * 96 + lane * 3 + 1] = u1;
        g_v[n * 96 + lane * 3 + 2] = u2;
        g_skip_v[n * 96 + lane * 3]     = k0;
        g_skip_v[n * 96 + lane * 3 + 1] = k1;
        g_skip_v[n * 96 + lane * 3 + 2] = k2;
        __syncwarp();
    }
}

// ---------------- kernel 2: fused edge MLP (fp32x2 packed) + scatter ----------------
__global__ void __launch_bounds__(384) edge_kernel(
    const float* __restrict__ radial, const float* __restrict__ Y0,
    const float* __restrict__ Y1,
    const int* __restrict__ senders, const int* __restrict__ receivers,
    const float* __restrict__ Wm1, const float* __restrict__ Wm2,
    const float* __restrict__ Wm3)
{
    extern __shared__ float sm[];
    float* sWm1 = sm;                 // 512
    float* sWm2 = sWm1 + 512;         // 4096
    float* sWm3 = sWm2 + 4096;        // 18432
    float* wb   = sWm3 + 18432;

    int tid = threadIdx.x, w = tid >> 5, lane = tid & 31;
    for (int i = tid; i < 512;   i += blockDim.x) sWm1[i] = Wm1[i];
    for (int i = tid; i < 4096;  i += blockDim.x) sWm2[i] = Wm2[i];
    for (int i = tid; i < 18432; i += blockDim.x) sWm3[i] = Wm3[i];
    __syncthreads();

    const int perW = 512 + 512 + 544;   // h1(pairs) + h2(pairs) + msg
    float* h1f = wb + w * perW;
    float* h2f = h1f + 512;
    float* msg = h2f + 512;
    ull* h1u = (ull*)h1f;
    ull* h2u = (ull*)h2f;

    int nwarps = gridDim.x * 12;
    int gw = blockIdx.x * 12 + w;
    const float inv_s3 = 0.57735026918962576f;

    for (int e0 = gw * EPB; e0 < Ee; e0 += nwarps * EPB) {
        // ---- layer 1 ----
        #pragma unroll
        for (int p = 0; p < NPAIR; p++) {
            float sv[2][2];
            #pragma unroll
            for (int hh = 0; hh < 2; hh++) {
                int e = e0 + 2 * p + hh;
                float rv = (lane < 8) ? radial[e * 8 + lane] : 0.f;
                float a0 = 0.f, a1 = 0.f;
                #pragma unroll
                for (int k = 0; k < 8; k++) {
                    float rk = __shfl_sync(0xffffffffu, rv, k);
                    a0 = fmaf(rk, sWm1[k * 64 + lane],      a0);
                    a1 = fmaf(rk, sWm1[k * 64 + lane + 32], a1);
                }
                sv[hh][0] = silu_f(a0);
                sv[hh][1] = silu_f(a1);
            }
            h1u[p * 64 + lane]      = pack2(sv[0][0], sv[1][0]);
            h1u[p * 64 + lane + 32] = pack2(sv[0][1], sv[1][1]);
        }
        __syncwarp();

        // ---- layer 2 ----
        {
            ull acc0[NPAIR], acc1[NPAIR];
            #pragma unroll
            for (int p = 0; p < NPAIR; p++) { acc0[p] = 0ull; acc1[p] = 0ull; }
            for (int k = 0; k < 64; k++) {
                float w0 = sWm2[k * 64 + lane];
                float w1 = sWm2[k * 64 + lane + 32];
                ull w0p = dup2(w0);
                ull w1p = dup2(w1);
                #pragma unroll
                for (int p = 0; p < NPAIR; p++) {
                    ull hp = h1u[p * 64 + k];
                    acc0[p] = fma2(hp, w0p, acc0[p]);
                    acc1[p] = fma2(hp, w1p, acc1[p]);
                }
            }
            #pragma unroll
            for (int p = 0; p < NPAIR; p++) {
                float x, y;
                unpack2(acc0[p], x, y);
                h2u[p * 64 + lane] = pack2(silu_f(x), silu_f(y));
                unpack2(acc1[p], x, y);
                h2u[p * 64 + lane + 32] = pack2(silu_f(x), silu_f(y));
            }
        }
        __syncwarp();

        // ---- layer 3 ----
        ull m2[NPAIR * 9];
        #pragma unroll
        for (int i = 0; i < NPAIR * 9; i++) m2[i] = 0ull;

        for (int k = 0; k < 64; k++) {
            ull hp[NPAIR];
            #pragma unroll
            for (int p = 0; p < NPAIR; p++) hp[p] = h2u[p * 64 + k];
            #pragma unroll
            for (int r = 0; r < 9; r++) {
                float wv = sWm3[k * 288 + lane + 32 * r];
                ull wp = dup2(wv);
                #pragma unroll
                for (int p = 0; p < NPAIR; p++)
                    m2[p * 9 + r] = fma2(hp[p], wp, m2[p * 9 + r]);
            }
        }

        // ---- messages + scatter ----
        #pragma unroll
        for (int t = 0; t < EPB; t++) {
            int pp = t >> 1, hh = t & 1;
            float mr[9];
            #pragma unroll
            for (int r = 0; r < 9; r++) {
                float lo, hi;
                unpack2(m2[pp * 9 + r], lo, hi);
                mr[r] = hh ? hi : lo;
            }
            int e = e0 + t;
            int snd = senders[e];
            int rcv = receivers[e];
            float m0  = g_s[snd * 64 + lane];
            float m1  = g_s[snd * 64 + lane + 32];
            float mv0 = g_v[snd * 96 + lane * 3];
            float mv1 = g_v[snd * 96 + lane * 3 + 1];
            float mv2 = g_v[snd * 96 + lane * 3 + 2];
            float y0  = Y0[e];
            float y10 = Y1[e * 3], y11 = Y1[e * 3 + 1], y12 = Y1[e * 3 + 2];
            float dot = (mv0 * y10 + mv1 * y11 + mv2 * y12) * inv_s3;

            msg[lane]       = m0 * mr[0];
            msg[32 + lane]  = m1 * mr[1];
            msg[64 + lane]  = m0 * y0 * mr[2];
            msg[96 + lane]  = m1 * y0 * mr[3];
            msg[128 + lane] = dot * mr[4];
            int b0 = 160 + lane * 3;
            msg[b0]     = mv0 * mr[5];
            msg[b0 + 1] = mv1 * mr[5];
            msg[b0 + 2] = mv2 * mr[5];
            int b1 = 160 + (32 + lane) * 3;
            float f6 = m0 * mr[6];
            msg[b1]     = f6 * y10;
            msg[b1 + 1] = f6 * y11;
            msg[b1 + 2] = f6 * y12;
            int b2 = 160 + (64 + lane) * 3;
            float f7 = m1 * mr[7];
            msg[b2]     = f7 * y10;
            msg[b2 + 1] = f7 * y11;
            msg[b2 + 2] = f7 * y12;
            int b3 = 160 + (96 + lane) * 3;
            float f8 = y0 * mr[8];
            msg[b3]     = mv0 * f8;
            msg[b3 + 1] = mv1 * f8;
            msg[b3 + 2] = mv2 * f8;
            __syncwarp();

            float* aggs = g_agg_s + (long)rcv * NSs;
            float* aggv = g_agg_v + (long)rcv * (NVv * 3);
            const float4* m4 = (const float4*)msg;
            #pragma unroll
            for (int gi = 0; gi < 5; gi++) {
                int g = lane + gi * 32;
                if (g < 136) {
                    float4 vv = m4[g];
                    float* p = (g < 40) ? (aggs + 4 * g) : (aggv + 4 * (g - 40));
                    asm volatile("red.global.add.v4.f32 [%0], {%1, %2, %3, %4};"
                                 :: "l"(p), "f"(vv.x), "f"(vv.y), "f"(vv.z), "f"(vv.w)
                                 : "memory");
                }
            }
            __syncwarp();
        }
    }
}

// ---------------- templated small-N GEMM, fp32x2 register-tiled ----------------
// 256 threads; thread owns TM rows x 4 cols. Full K kept in smem (weights reused
// BM times). AMODE: 0 = row-major A (lda=K); 1 = agg_v strided view
// (A[r,k] = Ag[(r/3)*384 + k*3 + r%3]).
// CMODE: 0 = C[row*N+c] = acc*scale; 2 = outS: C[row*64+c] = acc + skip[row*64+c];
//        3 = outV scatter: C[n*96 + c*3 + i] = acc + skip[...], row = 3n+i.
template<int K, int N, int BM, int AMODE, int CMODE>
__global__ void __launch_bounds__(256) gemm_kernel(
    const float* __restrict__ A, const float* __restrict__ B,
    const float* __restrict__ skip, float* __restrict__ C, float scale)
{
    constexpr int TX = N / 4;
    constexpr int TY = 256 / TX;
    constexpr int TM = BM / TY;
    constexpr int KP = K + 1;
    constexpr int NP = N + 2;
    extern __shared__ float smg[];
    float* sA = smg;             // BM*KP
    float* sB = sA + BM * KP;    // K*NP

    int t = threadIdx.x;
    int row0 = blockIdx.x * BM;

    for (int i = t; i < BM * K; i += 256) {
        int r = i / K, k = i - r * K;
        float v;
        if (AMODE == 0) {
            v = A[(long)(row0 + r) * K + k];
        } else {
            int rr = row0 + r;
            int n = rr / 3, ii = rr - 3 * n;
            v = A[(long)n * 384 + k * 3 + ii];
        }
        sA[r * KP + k] = v;
    }
    for (int i = t; i < K * N; i += 256) {
        int r = i / N, c = i - r * N;
        sB[r * NP + c] = B[i];
    }
    __syncthreads();

    int tx = t % TX, ty = t / TX;
    ull acc[TM][2];
    #pragma unroll
    for (int mi = 0; mi < TM; mi++) { acc[mi][0] = 0ull; acc[mi][1] = 0ull; }

    const float* aBase = sA + ty * TM * KP;
    const float* bBase = sB + 4 * tx;

    #pragma unroll 8
    for (int k = 0; k < K; k++) {
        ull b0 = lds64(bBase + k * NP);
        ull b1 = lds64(bBase + k * NP + 2);
        #pragma unroll
        for (int mi = 0; mi < TM; mi++) {
            ull ad = dup2(aBase[mi * KP + k]);
            acc[mi][0] = fma2(b0, ad, acc[mi][0]);
            acc[mi][1] = fma2(b1, ad, acc[mi][1]);
        }
    }

    #pragma unroll
    for (int mi = 0; mi < TM; mi++) {
        int row = row0 + ty * TM + mi;
        float v0, v1, v2, v3;
        unpack2(acc[mi][0], v0, v1);
        unpack2(acc[mi][1], v2, v3);
        if (CMODE == 0) {
            float4 o = make_float4(v0 * scale, v1 * scale, v2 * scale, v3 * scale);
            *(float4*)(C + (long)row * N + 4 * tx) = o;
        } else if (CMODE == 2) {
            float4 sk = *(const float4*)(skip + (long)row * 64 + 4 * tx);
            float4 o = make_float4(v0 + sk.x, v1 + sk.y, v2 + sk.z, v3 + sk.w);
            *(float4*)(C + (long)row * 64 + 4 * tx) = o;
        } else {
            int n = row / 3, ii = row - 3 * n;
            float vv[4] = {v0, v1, v2, v3};
            #pragma unroll
            for (int j = 0; j < 4; j++) {
                int c = 4 * tx + j;
                C[(long)n * 96 + c * 3 + ii] = vv[j] + skip[(long)n * 96 + c * 3 + ii];
            }
        }
    }
}

// ---------------- expansion: ts = x (x) s1, tv = x (x) v1 ----------------
// 1,310,720 float4 outputs = 5120 blocks * 256 threads
__global__ void __launch_bounds__(256) expand_kernel(const float* __restrict__ x_node) {
    int idx = blockIdx.x * 256 + threadIdx.x;
    if (idx < Nn * 64) {               // ts: float4 id = n*64 + a*16 + c4
        int n  = idx >> 6;
        int a  = (idx >> 4) & 3;
        int c4 = idx & 15;
        float x = x_node[n * 4 + a];
        float4 s = ((const float4*)g_s1)[n * 16 + c4];
        ((float4*)g_ts)[idx] = make_float4(x * s.x, x * s.y, x * s.z, x * s.w);
    } else {                           // tv: float4 id2 = r*32 + a*8 + c4
        int id2 = idx - Nn * 64;
        int r  = id2 >> 5;
        int a  = (id2 >> 3) & 3;
        int c4 = id2 & 7;
        float x = x_node[(r / 3) * 4 + a];
        float4 v = ((const float4*)g_v1)[r * 8 + c4];
        ((float4*)g_tv)[id2] = make_float4(x * v.x, x * v.y, x * v.z, x * v.w);
    }
}

// ---------------- quantum head: warp per node ----------------
__global__ void __launch_bounds__(256) quantum_kernel(
    const float* __restrict__ sfin,    // outS [Nn,64]
    const float* __restrict__ Wq, const float* __restrict__ wqml,
    const float* __restrict__ Wo, const float* __restrict__ bo,
    float* __restrict__ out0)
{
    __shared__ float sWq[512], cw[24], sw_[24], sWo[8];
    int tid = threadIdx.x;
    for (int i = tid; i < 512; i += 256) sWq[i] = Wq[i];
    if (tid < 24) {
        float ang = 0.5f * wqml[tid];
        cw[tid]  = cosf(ang);
        sw_[tid] = sinf(ang);
    }
    if (tid < 8) sWo[tid] = Wo[tid];
    __syncthreads();

    int w = tid >> 5, lane = tid & 31;
    int n = blockIdx.x * 8 + w;

    float s_lo = sfin[n * 64 + lane];
    float s_hi = sfin[n * 64 + lane + 32];

    // feats = s @ Wq : lane-partial + butterfly reduce (all lanes get all 8)
    float frow[8];
    #pragma unroll
    for (int q = 0; q < 8; q++)
        frow[q] = s_lo * sWq[lane * 8 + q] + s_hi * sWq[(lane + 32) * 8 + q];
    #pragma unroll
    for (int q = 0; q < 8; q++) {
        #pragma unroll
        for (int off = 16; off > 0; off >>= 1)
            frow[q] += __shfl_xor_sync(0xffffffffu, frow[q], off);
    }

    // ---- quantum circuit: idx = lane*8 + l; qubit q <-> idx bit (7-q) ----
    float cs[8], sn[8];
    #pragma unroll
    for (int q = 0; q < 8; q++) {
        float a = 0.5f * frow[q];
        __sincosf(a, &sn[q], &cs[q]);
    }
    float lf = 1.f;
    #pragma unroll
    for (int j = 0; j < 5; j++) {
        int q = 4 - j;
        lf *= ((lane >> j) & 1) ? sn[q] : cs[q];
    }
    float amp[8];
    #pragma unroll
    for (int l = 0; l < 8; l++) {
        float f = lf;
        f *= (l & 4) ? sn[5] : cs[5];
        f *= (l & 2) ? sn[6] : cs[6];
        f *= (l & 1) ? sn[7] : cs[7];
        amp[l] = f;
    }

    #pragma unroll
    for (int L = 0; L < 3; L++) {
        #pragma unroll
        for (int q = 0; q < 8; q++) {
            float c = cw[L * 8 + q], s = sw_[L * 8 + q];
            const int b = 7 - q;
            if (b >= 3) {
                const int m = 1 << (b - 3);
                int bit = (lane >> (b - 3)) & 1;
                #pragma unroll
                for (int l = 0; l < 8; l++) {
                    float p = __shfl_xor_sync(0xffffffffu, amp[l], m);
                    amp[l] = bit ? fmaf(s, p, c * amp[l]) : (c * amp[l] - s * p);
                }
            } else {
                const int tm = 1 << b;
                #pragma unroll
                for (int l = 0; l < 8; l++) {
                    if (!(l & tm)) {
                        float a0 = amp[l], a1 = amp[l | tm];
                        amp[l]      = c * a0 - s * a1;
                        amp[l | tm] = fmaf(s, a0, c * a1);
                    }
                }
            }
        }
        #pragma unroll
        for (int q = 0; q < 8; q++) {
            const int bc = 7 - q;
            const int bt = 7 - ((q + 1) & 7);
            if (bt >= 3) {
                const int m = 1 << (bt - 3);
                #pragma unroll
                for (int l = 0; l < 8; l++) {
                    float p = __shfl_xor_sync(0xffffffffu, amp[l], m);
                    int ctrl = (bc >= 3) ? ((lane >> (bc - 3)) & 1) : ((l >> bc) & 1);
                    amp[l] = ctrl ? p : amp[l];
                }
            } else {
                const int tm = 1 << bt;
                if (bc >= 3) {
                    int ctrl = (lane >> (bc - 3)) & 1;
                    #pragma unroll
                    for (int l = 0; l < 8; l++) {
                        if (!(l & tm)) {
                            float a = amp[l], bb = amp[l | tm];
                            amp[l]      = ctrl ? bb : a;
                            amp[l | tm] = ctrl ? a : bb;
                        }
                    }
                } else {
                    #pragma unroll
                    for (int l = 0; l < 8; l++) {
                        if (!(l & tm) && ((l >> bc) & 1)) {
                            float tmp = amp[l];
                            amp[l] = amp[l | tm];
                            amp[l | tm] = tmp;
                        }
                    }
                }
            }
        }
    }

    float tsum = 0.f, tb0 = 0.f, tb1 = 0.f, tb2 = 0.f;
    #pragma unroll
    for (int l = 0; l < 8; l++) {
        float p = amp[l] * amp[l];
        tsum += p;
        tb0 += (l & 1) ? -p : p;
        tb1 += (l & 2) ? -p : p;
        tb2 += (l & 4) ? -p : p;
    }
    float lanesum = 0.f;
    #pragma unroll
    for (int q = 0; q < 5; q++) {
        float sgn = ((lane >> (4 - q)) & 1) ? -1.f : 1.f;
        lanesum = fmaf(sgn * sWo[q], 1.f, lanesum);
    }
    float op = sWo[7] * tb0 + sWo[6] * tb1 + sWo[5] * tb2 + tsum * lanesum;
    #pragma unroll
    for (int o = 16; o > 0; o >>= 1)
        op += __shfl_xor_sync(0xffffffffu, op, o);
    if (lane == 0) out0[n] = op + bo[0];
}

// ---------------- launch ----------------
extern "C" void kernel_launch(void* const* d_in, const int* in_sizes, int n_in,
                              void* d_out, int out_size) {
    const float* s_in     = (const float*)d_in[0];
    const float* v_in     = (const float*)d_in[1];
    const float* x_node   = (const float*)d_in[2];
    const float* radial   = (const float*)d_in[3];
    const float* Y0       = (const float*)d_in[4];
    const float* Y1       = (const float*)d_in[5];
    const int*   species  = (const int*)d_in[6];
    const int*   senders  = (const int*)d_in[7];
    const int*   receivers= (const int*)d_in[8];
    const float* Wskip0   = (const float*)d_in[9];
    const float* Wskip1   = (const float*)d_in[10];
    const float* Wu0      = (const float*)d_in[11];
    const float* Wu1      = (const float*)d_in[12];
    const float* Wm1      = (const float*)d_in[13];
    const float* Wm2      = (const float*)d_in[14];
    const float* Wm3      = (const float*)d_in[15];
    const float* Wd0      = (const float*)d_in[16];
    const float* Wd1      = (const float*)d_in[17];
    const float* Wt0      = (const float*)d_in[18];
    const float* Wt1      = (const float*)d_in[19];
    const float* Wq       = (const float*)d_in[20];
    const float* wqml     = (const float*)d_in[21];
    const float* Wo       = (const float*)d_in[22];
    const float* bo       = (const float*)d_in[23];

    float* out0 = (float*)d_out;
    float* outS = out0 + Nn;
    float* outV = outS + Nn * C0;

    float* d_s1; cudaGetSymbolAddress((void**)&d_s1, g_s1);
    float* d_v1; cudaGetSymbolAddress((void**)&d_v1, g_v1);
    float* d_ts; cudaGetSymbolAddress((void**)&d_ts, g_ts);
    float* d_tv; cudaGetSymbolAddress((void**)&d_tv, g_tv);
    float* d_aggs; cudaGetSymbolAddress((void**)&d_aggs, g_agg_s);
    float* d_aggv; cudaGetSymbolAddress((void**)&d_aggv, g_agg_v);
    float* d_sks; cudaGetSymbolAddress((void**)&d_sks, g_skip_s);
    float* d_skv; cudaGetSymbolAddress((void**)&d_skv, g_skip_v);

    static bool attr_done = false;
    size_t smem_pre  = (4096 + 1024 + 16384 + 4096 + 8 * 160) * sizeof(float);
    size_t smem_edge = (512 + 4096 + 18432 + 12 * (512 + 512 + 544)) * sizeof(float);
    size_t smem_g1a = (64 * 161 + 160 * 66) * sizeof(float);   // 83456
    size_t smem_g1b = (128 * 129 + 128 * 34) * sizeof(float);  // 83456
    size_t smem_g2a = (64 * 257 + 256 * 66) * sizeof(float);   // 133376
    size_t smem_g2b = (128 * 129 + 128 * 34) * sizeof(float);  // 83456
    if (!attr_done) {
        cudaFuncSetAttribute(node_pre_kernel,  cudaFuncAttributeMaxDynamicSharedMemorySize, (int)smem_pre);
        cudaFuncSetAttribute(edge_kernel,      cudaFuncAttributeMaxDynamicSharedMemorySize, (int)smem_edge);
        cudaFuncSetAttribute((const void*)gemm_kernel<160, 64, 64, 0, 0>,
                             cudaFuncAttributeMaxDynamicSharedMemorySize, (int)smem_g1a);
        cudaFuncSetAttribute((const void*)gemm_kernel<128, 32, 128, 1, 0>,
                             cudaFuncAttributeMaxDynamicSharedMemorySize, (int)smem_g1b);
        cudaFuncSetAttribute((const void*)gemm_kernel<256, 64, 64, 0, 2>,
                             cudaFuncAttributeMaxDynamicSharedMemorySize, (int)smem_g2a);
        cudaFuncSetAttribute((const void*)gemm_kernel<128, 32, 128, 0, 3>,
                             cudaFuncAttributeMaxDynamicSharedMemorySize, (int)smem_g2b);
        attr_done = true;
    }

    const float inv16 = 1.0f / 16.0f;

    zero_agg_kernel<<<1024, 256>>>();
    node_pre_kernel<<<296, 256, smem_pre>>>(s_in, v_in, species, Wskip0, Wskip1, Wu0, Wu1);
    edge_kernel<<<148, 384, smem_edge>>>(radial, Y0, Y1, senders, receivers, Wm1, Wm2, Wm3);

    // s1 = agg_s @ Wd0 / 16         [8192,160] x [160,64]
    gemm_kernel<160, 64, 64, 0, 0><<<Nn / 64, 256, smem_g1a>>>(d_aggs, Wd0, nullptr, d_s1, inv16);
    // v1 = agg_v @ Wd1 / 16         [24576,128] x [128,32] (strided A)
    gemm_kernel<128, 32, 128, 1, 0><<<Nn * 3 / 128, 256, smem_g1b>>>(d_aggv, Wd1, nullptr, d_v1, inv16);
    // ts/tv expansion
    expand_kernel<<<5120, 256>>>(x_node);
    // outS = ts @ Wt0 + skip_s      [8192,256] x [256,64]
    gemm_kernel<256, 64, 64, 0, 2><<<Nn / 64, 256, smem_g2a>>>(d_ts, Wt0, d_sks, outS, 1.0f);
    // outV = tv @ Wt1 + skip_v      [24576,128] x [128,32], scatter epilogue
    gemm_kernel<128, 32, 128, 0, 3><<<Nn * 3 / 128, 256, smem_g2b>>>(d_tv, Wt1, d_skv, outV, 1.0f);
    // quantum head
    quantum_kernel<<<Nn / 8, 256>>>(outS, Wq, wqml, Wo, bo, out0);
}

// round 6
// speedup vs baseline: 1.0802x; 1.0655x over previous
#include <cuda_runtime.h>
#include <math.h>

#define Nn 8192
#define Ee 131072
#define C0 64
#define C1 32
#define NSs 160     // 2*C0 + C1
#define NVv 128     // C0 + 2*C1
#define EPB 8       // edges per warp batch (edge kernel)
#define NPAIR 4     // EPB/2
#define EW 16       // warps per edge block

typedef unsigned long long ull;

// ---------------- static device scratch ----------------
__device__ float g_s[Nn * C0];
__device__ float g_v[Nn * C1 * 3];
__device__ float g_skip_s[Nn * C0];
__device__ float g_skip_v[Nn * C1 * 3];
__device__ float g_agg_s[Nn * NSs];
__device__ float g_agg_v[Nn * NVv * 3];
__device__ float g_s1[Nn * C0];          // s after Wd0
__device__ float g_v1[Nn * 3 * C1];      // v after Wd1, rows (3n+i)

__device__ __forceinline__ float silu_f(float x) {
    return __fdividef(x, 1.0f + __expf(-x));
}

// packed fp32x2 helpers (sm_100a): bit-exact dual fp32 FMA
__device__ __forceinline__ ull pack2(float x, float y) {
    ull r; asm("mov.b64 %0, {%1, %2};" : "=l"(r) : "f"(x), "f"(y)); return r;
}
__device__ __forceinline__ void unpack2(ull v, float& x, float& y) {
    asm("mov.b64 {%0, %1}, %2;" : "=f"(x), "=f"(y) : "l"(v));
}
__device__ __forceinline__ ull fma2(ull a, ull b, ull c) {
    ull d; asm("fma.rn.f32x2 %0, %1, %2, %3;" : "=l"(d) : "l"(a), "l"(b), "l"(c)); return d;
}
__device__ __forceinline__ ull dup2(float x) { return pack2(x, x); }
__device__ __forceinline__ ull lds64(const float* p) { return *(const ull*)p; }

// ---------------- kernel 0: zero aggregation buffers ----------------
__global__ void zero_agg_kernel() {
    long i = (long)blockIdx.x * blockDim.x + threadIdx.x;
    long stride = (long)gridDim.x * blockDim.x;
    float4* a = (float4*)g_agg_s;
    long na = (long)Nn * NSs / 4;
    for (long j = i; j < na; j += stride) a[j] = make_float4(0.f, 0.f, 0.f, 0.f);
    float4* b = (float4*)g_agg_v;
    long nb = (long)Nn * NVv * 3 / 4;
    for (long j = i; j < nb; j += stride) b[j] = make_float4(0.f, 0.f, 0.f, 0.f);
}

// ---------------- kernel 1: node pre (Wu0/Wu1 + skips) ----------------
__global__ void __launch_bounds__(256) node_pre_kernel(
    const float* __restrict__ s_in, const float* __restrict__ v_in,
    const int* __restrict__ species,
    const float* __restrict__ Wskip0, const float* __restrict__ Wskip1,
    const float* __restrict__ Wu0, const float* __restrict__ Wu1)
{
    extern __shared__ float sm[];
    float* sWu0 = sm;                  // 4096
    float* sWu1 = sWu0 + 4096;         // 1024
    float* sWs0 = sWu1 + 1024;         // 16384
    float* sWs1 = sWs0 + 16384;        // 4096
    float* bufs = sWs1 + 4096;         // 8 warps * 160

    int tid = threadIdx.x;
    for (int i = tid; i < 4096;  i += blockDim.x) sWu0[i] = Wu0[i];
    for (int i = tid; i < 1024;  i += blockDim.x) sWu1[i] = Wu1[i];
    for (int i = tid; i < 16384; i += blockDim.x) sWs0[i] = Wskip0[i];
    for (int i = tid; i < 4096;  i += blockDim.x) sWs1[i] = Wskip1[i];
    __syncthreads();

    int w = tid >> 5, lane = tid & 31;
    float* sb = bufs + w * 160;
    float* vb = sb + 64;
    int warpsTotal = gridDim.x * 8;

    for (int n = blockIdx.x * 8 + w; n < Nn; n += warpsTotal) {
        sb[lane]      = s_in[n * 64 + lane];
        sb[lane + 32] = s_in[n * 64 + lane + 32];
        vb[lane]      = v_in[n * 96 + lane];
        vb[lane + 32] = v_in[n * 96 + lane + 32];
        vb[lane + 64] = v_in[n * 96 + lane + 64];
        __syncwarp();
        int sp = species[n];
        const float* Ws0 = sWs0 + sp * 4096;
        const float* Ws1 = sWs1 + sp * 1024;

        float a0 = 0.f, a1 = 0.f, b0 = 0.f, b1 = 0.f;
        #pragma unroll 8
        for (int c = 0; c < 64; c++) {
            float x = sb[c];
            a0 = fmaf(x, sWu0[c * 64 + lane],      a0);
            a1 = fmaf(x, sWu0[c * 64 + lane + 32], a1);
            b0 = fmaf(x, Ws0[c * 64 + lane],       b0);
            b1 = fmaf(x, Ws0[c * 64 + lane + 32],  b1);
        }
        g_s[n * 64 + lane]      = a0;
        g_s[n * 64 + lane + 32] = a1;
        g_skip_s[n * 64 + lane]      = b0;
        g_skip_s[n * 64 + lane + 32] = b1;

        float u0 = 0.f, u1 = 0.f, u2 = 0.f, k0 = 0.f, k1 = 0.f, k2 = 0.f;
        #pragma unroll 8
        for (int c = 0; c < 32; c++) {
            float wu = sWu1[c * 32 + lane];
            float wk = Ws1[c * 32 + lane];
            float x0 = vb[c * 3], x1 = vb[c * 3 + 1], x2 = vb[c * 3 + 2];
            u0 = fmaf(x0, wu, u0); u1 = fmaf(x1, wu, u1); u2 = fmaf(x2, wu, u2);
            k0 = fmaf(x0, wk, k0); k1 = fmaf(x1, wk, k1); k2 = fmaf(x2, wk, k2);
        }
        g_v[n * 96 + lane * 3]     = u0;
        g_v[n * 96 + lane * 3 + 1] = u1;
        g_v[n * 96 + lane * 3 + 2] = u2;
        g_skip_v[n * 96 + lane * 3]     = k0;
        g_skip_v[n * 96 + lane * 3 + 1] = k1;
        g_skip_v[n * 96 + lane * 3 + 2] = k2;
        __syncwarp();
    }
}

// ---------------- kernel 2: fused edge MLP (fp32x2 packed) + scatter ----------------
__global__ void __launch_bounds__(32 * EW) edge_kernel(
    const float* __restrict__ radial, const float* __restrict__ Y0,
    const float* __restrict__ Y1,
    const int* __restrict__ senders, const int* __restrict__ receivers,
    const float* __restrict__ Wm1, const float* __restrict__ Wm2,
    const float* __restrict__ Wm3)
{
    extern __shared__ float sm[];
    float* sWm1 = sm;                 // 512
    float* sWm2 = sWm1 + 512;         // 4096
    float* sWm3 = sWm2 + 4096;        // 18432
    float* wb   = sWm3 + 18432;

    int tid = threadIdx.x, w = tid >> 5, lane = tid & 31;
    for (int i = tid; i < 512;   i += blockDim.x) sWm1[i] = Wm1[i];
    for (int i = tid; i < 4096;  i += blockDim.x) sWm2[i] = Wm2[i];
    for (int i = tid; i < 18432; i += blockDim.x) sWm3[i] = Wm3[i];
    __syncthreads();

    const int perW = 512 + 512 + 544;   // h1(pairs) + h2(pairs) + msg
    float* h1f = wb + w * perW;
    float* h2f = h1f + 512;
    float* msg = h2f + 512;
    ull* h1u = (ull*)h1f;
    ull* h2u = (ull*)h2f;

    int nwarps = gridDim.x * EW;
    int gw = blockIdx.x * EW + w;
    const float inv_s3 = 0.57735026918962576f;

    for (int e0 = gw * EPB; e0 < Ee; e0 += nwarps * EPB) {
        // ---- layer 1 ----
        #pragma unroll
        for (int p = 0; p < NPAIR; p++) {
            float sv[2][2];
            #pragma unroll
            for (int hh = 0; hh < 2; hh++) {
                int e = e0 + 2 * p + hh;
                float rv = (lane < 8) ? radial[e * 8 + lane] : 0.f;
                float a0 = 0.f, a1 = 0.f;
                #pragma unroll
                for (int k = 0; k < 8; k++) {
                    float rk = __shfl_sync(0xffffffffu, rv, k);
                    a0 = fmaf(rk, sWm1[k * 64 + lane],      a0);
                    a1 = fmaf(rk, sWm1[k * 64 + lane + 32], a1);
                }
                sv[hh][0] = silu_f(a0);
                sv[hh][1] = silu_f(a1);
            }
            h1u[p * 64 + lane]      = pack2(sv[0][0], sv[1][0]);
            h1u[p * 64 + lane + 32] = pack2(sv[0][1], sv[1][1]);
        }
        __syncwarp();

        // ---- layer 2 ----
        {
            ull acc0[NPAIR], acc1[NPAIR];
            #pragma unroll
            for (int p = 0; p < NPAIR; p++) { acc0[p] = 0ull; acc1[p] = 0ull; }
            for (int k = 0; k < 64; k++) {
                float w0 = sWm2[k * 64 + lane];
                float w1 = sWm2[k * 64 + lane + 32];
                ull w0p = dup2(w0);
                ull w1p = dup2(w1);
                #pragma unroll
                for (int p = 0; p < NPAIR; p++) {
                    ull hp = h1u[p * 64 + k];
                    acc0[p] = fma2(hp, w0p, acc0[p]);
                    acc1[p] = fma2(hp, w1p, acc1[p]);
                }
            }
            #pragma unroll
            for (int p = 0; p < NPAIR; p++) {
                float x, y;
                unpack2(acc0[p], x, y);
                h2u[p * 64 + lane] = pack2(silu_f(x), silu_f(y));
                unpack2(acc1[p], x, y);
                h2u[p * 64 + lane + 32] = pack2(silu_f(x), silu_f(y));
            }
        }
        __syncwarp();

        // ---- layer 3 ----
        ull m2[NPAIR * 9];
        #pragma unroll
        for (int i = 0; i < NPAIR * 9; i++) m2[i] = 0ull;

        for (int k = 0; k < 64; k++) {
            ull hp[NPAIR];
            #pragma unroll
            for (int p = 0; p < NPAIR; p++) hp[p] = h2u[p * 64 + k];
            #pragma unroll
            for (int r = 0; r < 9; r++) {
                float wv = sWm3[k * 288 + lane + 32 * r];
                ull wp = dup2(wv);
                #pragma unroll
                for (int p = 0; p < NPAIR; p++)
                    m2[p * 9 + r] = fma2(hp[p], wp, m2[p * 9 + r]);
            }
        }

        // ---- messages + scatter ----
        #pragma unroll
        for (int t = 0; t < EPB; t++) {
            int pp = t >> 1, hh = t & 1;
            float mr[9];
            #pragma unroll
            for (int r = 0; r < 9; r++) {
                float lo, hi;
                unpack2(m2[pp * 9 + r], lo, hi);
                mr[r] = hh ? hi : lo;
            }
            int e = e0 + t;
            int snd = senders[e];
            int rcv = receivers[e];
            float m0  = g_s[snd * 64 + lane];
            float m1  = g_s[snd * 64 + lane + 32];
            float mv0 = g_v[snd * 96 + lane * 3];
            float mv1 = g_v[snd * 96 + lane * 3 + 1];
            float mv2 = g_v[snd * 96 + lane * 3 + 2];
            float y0  = Y0[e];
            float y10 = Y1[e * 3], y11 = Y1[e * 3 + 1], y12 = Y1[e * 3 + 2];
            float dot = (mv0 * y10 + mv1 * y11 + mv2 * y12) * inv_s3;

            msg[lane]       = m0 * mr[0];
            msg[32 + lane]  = m1 * mr[1];
            msg[64 + lane]  = m0 * y0 * mr[2];
            msg[96 + lane]  = m1 * y0 * mr[3];
            msg[128 + lane] = dot * mr[4];
            int b0 = 160 + lane * 3;
            msg[b0]     = mv0 * mr[5];
            msg[b0 + 1] = mv1 * mr[5];
            msg[b0 + 2] = mv2 * mr[5];
            int b1 = 160 + (32 + lane) * 3;
            float f6 = m0 * mr[6];
            msg[b1]     = f6 * y10;
            msg[b1 + 1] = f6 * y11;
            msg[b1 + 2] = f6 * y12;
            int b2 = 160 + (64 + lane) * 3;
            float f7 = m1 * mr[7];
            msg[b2]     = f7 * y10;
            msg[b2 + 1] = f7 * y11;
            msg[b2 + 2] = f7 * y12;
            int b3 = 160 + (96 + lane) * 3;
            float f8 = y0 * mr[8];
            msg[b3]     = mv0 * f8;
            msg[b3 + 1] = mv1 * f8;
            msg[b3 + 2] = mv2 * f8;
            __syncwarp();

            float* aggs = g_agg_s + (long)rcv * NSs;
            float* aggv = g_agg_v + (long)rcv * (NVv * 3);
            const float4* m4 = (const float4*)msg;
            #pragma unroll
            for (int gi = 0; gi < 5; gi++) {
                int g = lane + gi * 32;
                if (g < 136) {
                    float4 vv = m4[g];
                    float* p = (g < 40) ? (aggs + 4 * g) : (aggv + 4 * (g - 40));
                    asm volatile("red.global.add.v4.f32 [%0], {%1, %2, %3, %4};"
                                 :: "l"(p), "f"(vv.x), "f"(vv.y), "f"(vv.z), "f"(vv.w)
                                 : "memory");
                }
            }
            __syncwarp();
        }
    }
}

// ---------------- device gemm body, fp32x2 register-tiled ----------------
// AMODE: 0 = row-major A; 1 = agg_v strided view; 2 = ts on-the-fly (A=g_s1);
//        3 = tv on-the-fly (A=g_v1).
// CMODE: 0 = C = acc*scale; 2 = outS = acc + skip (+ smem tile + quantum);
//        3 = outV scatter = acc + skip.
// sq (CMODE 2): [0:512) Wq, [512:536) cos, [536:560) sin, [560:568) Wo, [568] bo
template<int K, int N, int BM, int AMODE, int CMODE>
__device__ __forceinline__ void gemm_body(
    const float* __restrict__ A, const float* __restrict__ B,
    const float* __restrict__ skip, float* __restrict__ C, float scale,
    int bid, float* smg, const float* __restrict__ x_node,
    float* __restrict__ out0, const float* sq)
{
    constexpr int TX = N / 4;
    constexpr int TY = 256 / TX;
    constexpr int TM = BM / TY;
    constexpr int KP = K + 1;
    constexpr int NP = N + 2;
    float* sA = smg;             // BM*KP
    float* sB = sA + BM * KP;    // K*NP

    int t = threadIdx.x;
    int row0 = bid * BM;

    for (int i = t; i < BM * K; i += 256) {
        int r = i / K, k = i - r * K;
        int rr = row0 + r;
        float v;
        if (AMODE == 0) {
            v = A[(long)rr * K + k];
        } else if (AMODE == 1) {
            int n = rr / 3, ii = rr - 3 * n;
            v = A[(long)n * 384 + k * 3 + ii];
        } else if (AMODE == 2) {
            int a = k >> 6, c = k & 63;
            v = x_node[rr * 4 + a] * A[(long)rr * 64 + c];
        } else {
            int a = k >> 5, c = k & 31;
            v = x_node[(rr / 3) * 4 + a] * A[(long)rr * 32 + c];
        }
        sA[r * KP + k] = v;
    }
    for (int i = t; i < K * N; i += 256) {
        int r = i / N, c = i - r * N;
        sB[r * NP + c] = B[i];
    }
    __syncthreads();

    int tx = t % TX, ty = t / TX;
    ull acc[TM][2];
    #pragma unroll
    for (int mi = 0; mi < TM; mi++) { acc[mi][0] = 0ull; acc[mi][1] = 0ull; }

    const float* aBase = sA + ty * TM * KP;
    const float* bBase = sB + 4 * tx;

    #pragma unroll 8
    for (int k = 0; k < K; k++) {
        ull b0 = lds64(bBase + k * NP);
        ull b1 = lds64(bBase + k * NP + 2);
        #pragma unroll
        for (int mi = 0; mi < TM; mi++) {
            ull ad = dup2(aBase[mi * KP + k]);
            acc[mi][0] = fma2(b0, ad, acc[mi][0]);
            acc[mi][1] = fma2(b1, ad, acc[mi][1]);
        }
    }

    if (CMODE == 0) {
        #pragma unroll
        for (int mi = 0; mi < TM; mi++) {
            int row = row0 + ty * TM + mi;
            float v0, v1, v2, v3;
            unpack2(acc[mi][0], v0, v1);
            unpack2(acc[mi][1], v2, v3);
            float4 o = make_float4(v0 * scale, v1 * scale, v2 * scale, v3 * scale);
            *(float4*)(C + (long)row * N + 4 * tx) = o;
        }
    } else if (CMODE == 3) {
        #pragma unroll
        for (int mi = 0; mi < TM; mi++) {
            int row = row0 + ty * TM + mi;
            float vv[4];
            unpack2(acc[mi][0], vv[0], vv[1]);
            unpack2(acc[mi][1], vv[2], vv[3]);
            int n = row / 3, ii = row - 3 * n;
            #pragma unroll
            for (int j = 0; j < 4; j++) {
                int c = 4 * tx + j;
                C[(long)n * 96 + c * 3 + ii] = vv[j] + skip[(long)n * 96 + c * 3 + ii];
            }
        }
    } else {
        // CMODE 2: outS + smem tile + fused quantum head
        float ov[TM][4];
        #pragma unroll
        for (int mi = 0; mi < TM; mi++) {
            int row = row0 + ty * TM + mi;
            float v0, v1, v2, v3;
            unpack2(acc[mi][0], v0, v1);
            unpack2(acc[mi][1], v2, v3);
            float4 sk = *(const float4*)(skip + (long)row * 64 + 4 * tx);
            ov[mi][0] = v0 + sk.x; ov[mi][1] = v1 + sk.y;
            ov[mi][2] = v2 + sk.z; ov[mi][3] = v3 + sk.w;
        }
        __syncthreads();                 // done reading sA; reuse as output tile
        float* sOut = smg;               // 64 x 65
        #pragma unroll
        for (int mi = 0; mi < TM; mi++) {
            int r = ty * TM + mi;
            int row = row0 + r;
            *(float4*)(C + (long)row * 64 + 4 * tx) =
                make_float4(ov[mi][0], ov[mi][1], ov[mi][2], ov[mi][3]);
            sOut[r * 65 + 4 * tx]     = ov[mi][0];
            sOut[r * 65 + 4 * tx + 1] = ov[mi][1];
            sOut[r * 65 + 4 * tx + 2] = ov[mi][2];
            sOut[r * 65 + 4 * tx + 3] = ov[mi][3];
        }
        __syncthreads();

        const float* sWq = sq;
        const float* cw  = sq + 512;
        const float* sw_ = sq + 536;
        const float* sWo = sq + 560;
        float bo0 = sq[568];
        int w = t >> 5, lane = t & 31;

        #pragma unroll 1
        for (int pass = 0; pass < 8; pass++) {
            int r = pass * 8 + w;
            int n = row0 + r;
            const float* srow = sOut + r * 65;
            float s_lo = srow[lane];
            float s_hi = srow[lane + 32];

            float frow[8];
            #pragma unroll
            for (int q = 0; q < 8; q++)
                frow[q] = s_lo * sWq[lane * 8 + q] + s_hi * sWq[(lane + 32) * 8 + q];
            #pragma unroll
            for (int q = 0; q < 8; q++) {
                #pragma unroll
                for (int off = 16; off > 0; off >>= 1)
                    frow[q] += __shfl_xor_sync(0xffffffffu, frow[q], off);
            }

            float cs[8], sn[8];
            #pragma unroll
            for (int q = 0; q < 8; q++) {
                float a = 0.5f * frow[q];
                __sincosf(a, &sn[q], &cs[q]);
            }
            float lf = 1.f;
            #pragma unroll
            for (int j = 0; j < 5; j++) {
                int q = 4 - j;
                lf *= ((lane >> j) & 1) ? sn[q] : cs[q];
            }
            float amp[8];
            #pragma unroll
            for (int l = 0; l < 8; l++) {
                float f = lf;
                f *= (l & 4) ? sn[5] : cs[5];
                f *= (l & 2) ? sn[6] : cs[6];
                f *= (l & 1) ? sn[7] : cs[7];
                amp[l] = f;
            }

            #pragma unroll
            for (int L = 0; L < 3; L++) {
                #pragma unroll
                for (int q = 0; q < 8; q++) {
                    float c = cw[L * 8 + q], s = sw_[L * 8 + q];
                    const int b = 7 - q;
                    if (b >= 3) {
                        const int m = 1 << (b - 3);
                        int bit = (lane >> (b - 3)) & 1;
                        #pragma unroll
                        for (int l = 0; l < 8; l++) {
                            float p = __shfl_xor_sync(0xffffffffu, amp[l], m);
                            amp[l] = bit ? fmaf(s, p, c * amp[l]) : (c * amp[l] - s * p);
                        }
                    } else {
                        const int tm = 1 << b;
                        #pragma unroll
                        for (int l = 0; l < 8; l++) {
                            if (!(l & tm)) {
                                float a0 = amp[l], a1 = amp[l | tm];
                                amp[l]      = c * a0 - s * a1;
                                amp[l | tm] = fmaf(s, a0, c * a1);
                            }
                        }
                    }
                }
                #pragma unroll
                for (int q = 0; q < 8; q++) {
                    const int bc = 7 - q;
                    const int bt = 7 - ((q + 1) & 7);
                    if (bt >= 3) {
                        const int m = 1 << (bt - 3);
                        #pragma unroll
                        for (int l = 0; l < 8; l++) {
                            float p = __shfl_xor_sync(0xffffffffu, amp[l], m);
                            int ctrl = (bc >= 3) ? ((lane >> (bc - 3)) & 1) : ((l >> bc) & 1);
                            amp[l] = ctrl ? p : amp[l];
                        }
                    } else {
                        const int tm = 1 << bt;
                        if (bc >= 3) {
                            int ctrl = (lane >> (bc - 3)) & 1;
                            #pragma unroll
                            for (int l = 0; l < 8; l++) {
                                if (!(l & tm)) {
                                    float a = amp[l], bb = amp[l | tm];
                                    amp[l]      = ctrl ? bb : a;
                                    amp[l | tm] = ctrl ? a : bb;
                                }
                            }
                        } else {
                            #pragma unroll
                            for (int l = 0; l < 8; l++) {
                                if (!(l & tm) && ((l >> bc) & 1)) {
                                    float tmp = amp[l];
                                    amp[l] = amp[l | tm];
                                    amp[l | tm] = tmp;
                                }
                            }
                        }
                    }
                }
            }

            float tsum = 0.f, tb0 = 0.f, tb1 = 0.f, tb2 = 0.f;
            #pragma unroll
            for (int l = 0; l < 8; l++) {
                float p = amp[l] * amp[l];
                tsum += p;
                tb0 += (l & 1) ? -p : p;
                tb1 += (l & 2) ? -p : p;
                tb2 += (l & 4) ? -p : p;
            }
            float lanesum = 0.f;
            #pragma unroll
            for (int q = 0; q < 5; q++) {
                float sgn = ((lane >> (4 - q)) & 1) ? -1.f : 1.f;
                lanesum = fmaf(sgn * sWo[q], 1.f, lanesum);
            }
            float op = sWo[7] * tb0 + sWo[6] * tb1 + sWo[5] * tb2 + tsum * lanesum;
            #pragma unroll
            for (int o = 16; o > 0; o >>= 1)
                op += __shfl_xor_sync(0xffffffffu, op, o);
            if (lane == 0) out0[n] = op + bo0;
        }
    }
}

// ---------------- nodeA: both first-stage GEMMs in one launch ----------------
__global__ void __launch_bounds__(256) nodeA_kernel(
    const float* __restrict__ Wd0, const float* __restrict__ Wd1)
{
    extern __shared__ float smg[];
    const float inv16 = 1.0f / 16.0f;
    if (blockIdx.x < 128)
        gemm_body<160, 64, 64, 0, 0>(g_agg_s, Wd0, nullptr, g_s1, inv16,
                                     blockIdx.x, smg, nullptr, nullptr, nullptr);
    else
        gemm_body<128, 32, 128, 1, 0>(g_agg_v, Wd1, nullptr, g_v1, inv16,
                                      blockIdx.x - 128, smg, nullptr, nullptr, nullptr);
}

// ---------------- nodeB: both second-stage GEMMs + fused quantum head ----------------
__global__ void __launch_bounds__(256) nodeB_kernel(
    const float* __restrict__ Wt0, const float* __restrict__ Wt1,
    const float* __restrict__ x_node,
    const float* __restrict__ Wq, const float* __restrict__ wqml,
    const float* __restrict__ Wo, const float* __restrict__ bo,
    float* __restrict__ out0, float* __restrict__ outS, float* __restrict__ outV)
{
    extern __shared__ float smg[];
    float* sq = smg + 33344;
    int t = threadIdx.x;
    for (int i = t; i < 512; i += 256) sq[i] = Wq[i];
    if (t < 24) {
        float ang = 0.5f * wqml[t];
        sq[512 + t] = cosf(ang);
        sq[536 + t] = sinf(ang);
    }
    if (t < 8)  sq[560 + t] = Wo[t];
    if (t == 0) sq[568] = bo[0];
    __syncthreads();

    if (blockIdx.x < 128)
        gemm_body<256, 64, 64, 2, 2>(g_s1, Wt0, g_skip_s, outS, 1.0f,
                                     blockIdx.x, smg, x_node, out0, sq);
    else
        gemm_body<128, 32, 128, 3, 3>(g_v1, Wt1, g_skip_v, outV, 1.0f,
                                      blockIdx.x - 128, smg, x_node, nullptr, nullptr);
}

// ---------------- launch ----------------
extern "C" void kernel_launch(void* const* d_in, const int* in_sizes, int n_in,
                              void* d_out, int out_size) {
    const float* s_in     = (const float*)d_in[0];
    const float* v_in     = (const float*)d_in[1];
    const float* x_node   = (const float*)d_in[2];
    const float* radial   = (const float*)d_in[3];
    const float* Y0       = (const float*)d_in[4];
    const float* Y1       = (const float*)d_in[5];
    const int*   species  = (const int*)d_in[6];
    const int*   senders  = (const int*)d_in[7];
    const int*   receivers= (const int*)d_in[8];
    const float* Wskip0   = (const float*)d_in[9];
    const float* Wskip1   = (const float*)d_in[10];
    const float* Wu0      = (const float*)d_in[11];
    const float* Wu1      = (const float*)d_in[12];
    const float* Wm1      = (const float*)d_in[13];
    const float* Wm2      = (const float*)d_in[14];
    const float* Wm3      = (const float*)d_in[15];
    const float* Wd0      = (const float*)d_in[16];
    const float* Wd1      = (const float*)d_in[17];
    const float* Wt0      = (const float*)d_in[18];
    const float* Wt1      = (const float*)d_in[19];
    const float* Wq       = (const float*)d_in[20];
    const float* wqml     = (const float*)d_in[21];
    const float* Wo       = (const float*)d_in[22];
    const float* bo       = (const float*)d_in[23];

    float* out0 = (float*)d_out;
    float* outS = out0 + Nn;
    float* outV = outS + Nn * C0;

    static bool attr_done = false;
    size_t smem_pre   = (4096 + 1024 + 16384 + 4096 + 8 * 160) * sizeof(float);
    size_t smem_edge  = (512 + 4096 + 18432 + EW * 1568) * sizeof(float);
    size_t smem_nodeA = (20864) * sizeof(float);                 // 83.5 KB
    size_t smem_nodeB = (33344 + 576) * sizeof(float);           // ~135.7 KB
    if (!attr_done) {
        cudaFuncSetAttribute(node_pre_kernel, cudaFuncAttributeMaxDynamicSharedMemorySize, (int)smem_pre);
        cudaFuncSetAttribute(edge_kernel,     cudaFuncAttributeMaxDynamicSharedMemorySize, (int)smem_edge);
        cudaFuncSetAttribute(nodeA_kernel,    cudaFuncAttributeMaxDynamicSharedMemorySize, (int)smem_nodeA);
        cudaFuncSetAttribute(nodeB_kernel,    cudaFuncAttributeMaxDynamicSharedMemorySize, (int)smem_nodeB);
        attr_done = true;
    }

    zero_agg_kernel<<<1024, 256>>>();
    node_pre_kernel<<<296, 256, smem_pre>>>(s_in, v_in, species, Wskip0, Wskip1, Wu0, Wu1);
    edge_kernel<<<148, 32 * EW, smem_edge>>>(radial, Y0, Y1, senders, receivers, Wm1, Wm2, Wm3);
    nodeA_kernel<<<320, 256, smem_nodeA>>>(Wd0, Wd1);
    nodeB_kernel<<<320, 256, smem_nodeB>>>(Wt0, Wt1, x_node, Wq, wqml, Wo, bo, out0, outS, outV);
}

// round 7
// speedup vs baseline: 1.1965x; 1.1076x over previous
#include <cuda_runtime.h>
#include <math.h>

#define Nn 8192
#define Ee 131072
#define C0 64
#define C1 32
#define NSs 160     // 2*C0 + C1
#define NVv 128     // C0 + 2*C1
#define EPB 8       // edges per warp batch (edge kernel)
#define NPAIR 4     // EPB/2
#define EW 16       // warps per edge block

typedef unsigned long long ull;

// ---------------- static device scratch ----------------
__device__ float g_s[Nn * C0];
__device__ float g_v[Nn * C1 * 3];
__device__ float g_skip_s[Nn * C0];
__device__ float g_skip_v[Nn * C1 * 3];
__device__ float g_agg_s[Nn * NSs];
__device__ float g_agg_v[Nn * 3 * NVv];  // [n][ii][c]  (component-major!)
__device__ float g_s1[Nn * C0];          // s after Wd0
__device__ float g_v1[Nn * 3 * C1];      // v after Wd1, rows (3n+ii)

__device__ __forceinline__ float silu_f(float x) {
    return __fdividef(x, 1.0f + __expf(-x));
}

// packed fp32x2 helpers (sm_100a): bit-exact dual fp32 FMA
__device__ __forceinline__ ull pack2(float x, float y) {
    ull r; asm("mov.b64 %0, {%1, %2};" : "=l"(r) : "f"(x), "f"(y)); return r;
}
__device__ __forceinline__ void unpack2(ull v, float& x, float& y) {
    asm("mov.b64 {%0, %1}, %2;" : "=f"(x), "=f"(y) : "l"(v));
}
__device__ __forceinline__ ull fma2(ull a, ull b, ull c) {
    ull d; asm("fma.rn.f32x2 %0, %1, %2, %3;" : "=l"(d) : "l"(a), "l"(b), "l"(c)); return d;
}
__device__ __forceinline__ ull dup2(float x) { return pack2(x, x); }
__device__ __forceinline__ ull lds64(const float* p) { return *(const ull*)p; }

// ---------------- kernel 0: zero aggregation buffers ----------------
__global__ void zero_agg_kernel() {
    long i = (long)blockIdx.x * blockDim.x + threadIdx.x;
    long stride = (long)gridDim.x * blockDim.x;
    float4* a = (float4*)g_agg_s;
    long na = (long)Nn * NSs / 4;
    for (long j = i; j < na; j += stride) a[j] = make_float4(0.f, 0.f, 0.f, 0.f);
    float4* b = (float4*)g_agg_v;
    long nb = (long)Nn * NVv * 3 / 4;
    for (long j = i; j < nb; j += stride) b[j] = make_float4(0.f, 0.f, 0.f, 0.f);
}

// ---------------- kernel 1: node pre (Wu0/Wu1 + skips) ----------------
__global__ void __launch_bounds__(256) node_pre_kernel(
    const float* __restrict__ s_in, const float* __restrict__ v_in,
    const int* __restrict__ species,
    const float* __restrict__ Wskip0, const float* __restrict__ Wskip1,
    const float* __restrict__ Wu0, const float* __restrict__ Wu1)
{
    extern __shared__ float sm[];
    float* sWu0 = sm;                  // 4096
    float* sWu1 = sWu0 + 4096;         // 1024
    float* sWs0 = sWu1 + 1024;         // 16384
    float* sWs1 = sWs0 + 16384;        // 4096
    float* bufs = sWs1 + 4096;         // 8 warps * 160

    int tid = threadIdx.x;
    for (int i = tid; i < 4096;  i += blockDim.x) sWu0[i] = Wu0[i];
    for (int i = tid; i < 1024;  i += blockDim.x) sWu1[i] = Wu1[i];
    for (int i = tid; i < 16384; i += blockDim.x) sWs0[i] = Wskip0[i];
    for (int i = tid; i < 4096;  i += blockDim.x) sWs1[i] = Wskip1[i];
    __syncthreads();

    int w = tid >> 5, lane = tid & 31;
    float* sb = bufs + w * 160;
    float* vb = sb + 64;
    int warpsTotal = gridDim.x * 8;

    for (int n = blockIdx.x * 8 + w; n < Nn; n += warpsTotal) {
        sb[lane]      = s_in[n * 64 + lane];
        sb[lane + 32] = s_in[n * 64 + lane + 32];
        vb[lane]      = v_in[n * 96 + lane];
        vb[lane + 32] = v_in[n * 96 + lane + 32];
        vb[lane + 64] = v_in[n * 96 + lane + 64];
        __syncwarp();
        int sp = species[n];
        const float* Ws0 = sWs0 + sp * 4096;
        const float* Ws1 = sWs1 + sp * 1024;

        float a0 = 0.f, a1 = 0.f, b0 = 0.f, b1 = 0.f;
        #pragma unroll 8
        for (int c = 0; c < 64; c++) {
            float x = sb[c];
            a0 = fmaf(x, sWu0[c * 64 + lane],      a0);
            a1 = fmaf(x, sWu0[c * 64 + lane + 32], a1);
            b0 = fmaf(x, Ws0[c * 64 + lane],       b0);
            b1 = fmaf(x, Ws0[c * 64 + lane + 32],  b1);
        }
        g_s[n * 64 + lane]      = a0;
        g_s[n * 64 + lane + 32] = a1;
        g_skip_s[n * 64 + lane]      = b0;
        g_skip_s[n * 64 + lane + 32] = b1;

        float u0 = 0.f, u1 = 0.f, u2 = 0.f, k0 = 0.f, k1 = 0.f, k2 = 0.f;
        #pragma unroll 8
        for (int c = 0; c < 32; c++) {
            float wu = sWu1[c * 32 + lane];
            float wk = Ws1[c * 32 + lane];
            float x0 = vb[c * 3], x1 = vb[c * 3 + 1], x2 = vb[c * 3 + 2];
            u0 = fmaf(x0, wu, u0); u1 = fmaf(x1, wu, u1); u2 = fmaf(x2, wu, u2);
            k0 = fmaf(x0, wk, k0); k1 = fmaf(x1, wk, k1); k2 = fmaf(x2, wk, k2);
        }
        g_v[n * 96 + lane * 3]     = u0;
        g_v[n * 96 + lane * 3 + 1] = u1;
        g_v[n * 96 + lane * 3 + 2] = u2;
        g_skip_v[n * 96 + lane * 3]     = k0;
        g_skip_v[n * 96 + lane * 3 + 1] = k1;
        g_skip_v[n * 96 + lane * 3 + 2] = k2;
        __syncwarp();
    }
}

// ---------------- kernel 2: fused edge MLP (fp32x2 packed) + scatter ----------------
// msg layout: [0:160) scalar channels; [160:544) vector part [ii][c] (c in 0..127)
__global__ void __launch_bounds__(32 * EW) edge_kernel(
    const float* __restrict__ radial, const float* __restrict__ Y0,
    const float* __restrict__ Y1,
    const int* __restrict__ senders, const int* __restrict__ receivers,
    const float* __restrict__ Wm1, const float* __restrict__ Wm2,
    const float* __restrict__ Wm3)
{
    extern __shared__ float sm[];
    float* sWm1 = sm;                 // 512
    float* sWm2 = sWm1 + 512;         // 4096
    float* sWm3 = sWm2 + 4096;        // 18432
    float* wb   = sWm3 + 18432;

    int tid = threadIdx.x, w = tid >> 5, lane = tid & 31;
    for (int i = tid; i < 512;   i += blockDim.x) sWm1[i] = Wm1[i];
    for (int i = tid; i < 4096;  i += blockDim.x) sWm2[i] = Wm2[i];
    for (int i = tid; i < 18432; i += blockDim.x) sWm3[i] = Wm3[i];
    __syncthreads();

    const int perW = 512 + 512 + 544;   // h1(pairs) + h2(pairs) + msg
    float* h1f = wb + w * perW;
    float* h2f = h1f + 512;
    float* msg = h2f + 512;
    ull* h1u = (ull*)h1f;
    ull* h2u = (ull*)h2f;

    int nwarps = gridDim.x * EW;
    int gw = blockIdx.x * EW + w;
    const float inv_s3 = 0.57735026918962576f;

    for (int e0 = gw * EPB; e0 < Ee; e0 += nwarps * EPB) {
        // ---- layer 1 ----
        #pragma unroll
        for (int p = 0; p < NPAIR; p++) {
            float sv[2][2];
            #pragma unroll
            for (int hh = 0; hh < 2; hh++) {
                int e = e0 + 2 * p + hh;
                float rv = (lane < 8) ? radial[e * 8 + lane] : 0.f;
                float a0 = 0.f, a1 = 0.f;
                #pragma unroll
                for (int k = 0; k < 8; k++) {
                    float rk = __shfl_sync(0xffffffffu, rv, k);
                    a0 = fmaf(rk, sWm1[k * 64 + lane],      a0);
                    a1 = fmaf(rk, sWm1[k * 64 + lane + 32], a1);
                }
                sv[hh][0] = silu_f(a0);
                sv[hh][1] = silu_f(a1);
            }
            h1u[p * 64 + lane]      = pack2(sv[0][0], sv[1][0]);
            h1u[p * 64 + lane + 32] = pack2(sv[0][1], sv[1][1]);
        }
        __syncwarp();

        // ---- layer 2 ----
        {
            ull acc0[NPAIR], acc1[NPAIR];
            #pragma unroll
            for (int p = 0; p < NPAIR; p++) { acc0[p] = 0ull; acc1[p] = 0ull; }
            for (int k = 0; k < 64; k++) {
                float w0 = sWm2[k * 64 + lane];
                float w1 = sWm2[k * 64 + lane + 32];
                ull w0p = dup2(w0);
                ull w1p = dup2(w1);
                #pragma unroll
                for (int p = 0; p < NPAIR; p++) {
                    ull hp = h1u[p * 64 + k];
                    acc0[p] = fma2(hp, w0p, acc0[p]);
                    acc1[p] = fma2(hp, w1p, acc1[p]);
                }
            }
            #pragma unroll
            for (int p = 0; p < NPAIR; p++) {
                float x, y;
                unpack2(acc0[p], x, y);
                h2u[p * 64 + lane] = pack2(silu_f(x), silu_f(y));
                unpack2(acc1[p], x, y);
                h2u[p * 64 + lane + 32] = pack2(silu_f(x), silu_f(y));
            }
        }
        __syncwarp();

        // ---- layer 3 ----
        ull m2[NPAIR * 9];
        #pragma unroll
        for (int i = 0; i < NPAIR * 9; i++) m2[i] = 0ull;

        for (int k = 0; k < 64; k++) {
            ull hp[NPAIR];
            #pragma unroll
            for (int p = 0; p < NPAIR; p++) hp[p] = h2u[p * 64 + k];
            #pragma unroll
            for (int r = 0; r < 9; r++) {
                float wv = sWm3[k * 288 + lane + 32 * r];
                ull wp = dup2(wv);
                #pragma unroll
                for (int p = 0; p < NPAIR; p++)
                    m2[p * 9 + r] = fma2(hp[p], wp, m2[p * 9 + r]);
            }
        }

        // ---- messages + scatter ----
        #pragma unroll
        for (int t = 0; t < EPB; t++) {
            int pp = t >> 1, hh = t & 1;
            float mr[9];
            #pragma unroll
            for (int r = 0; r < 9; r++) {
                float lo, hi;
                unpack2(m2[pp * 9 + r], lo, hi);
                mr[r] = hh ? hi : lo;
            }
            int e = e0 + t;
            int snd = senders[e];
            int rcv = receivers[e];
            float m0  = g_s[snd * 64 + lane];
            float m1  = g_s[snd * 64 + lane + 32];
            float mv0 = g_v[snd * 96 + lane * 3];
            float mv1 = g_v[snd * 96 + lane * 3 + 1];
            float mv2 = g_v[snd * 96 + lane * 3 + 2];
            float y0  = Y0[e];
            float y10 = Y1[e * 3], y11 = Y1[e * 3 + 1], y12 = Y1[e * 3 + 2];
            float dot = (mv0 * y10 + mv1 * y11 + mv2 * y12) * inv_s3;

            msg[lane]       = m0 * mr[0];
            msg[32 + lane]  = m1 * mr[1];
            msg[64 + lane]  = m0 * y0 * mr[2];
            msg[96 + lane]  = m1 * y0 * mr[3];
            msg[128 + lane] = dot * mr[4];
            // vector part, component-major: msg[160 + ii*128 + ch]
            float vv5 = mr[5];
            msg[160 + lane]       = mv0 * vv5;
            msg[160 + 128 + lane] = mv1 * vv5;
            msg[160 + 256 + lane] = mv2 * vv5;
            float f6 = m0 * mr[6];
            msg[160 + 32 + lane]        = f6 * y10;
            msg[160 + 128 + 32 + lane]  = f6 * y11;
            msg[160 + 256 + 32 + lane]  = f6 * y12;
            float f7 = m1 * mr[7];
            msg[160 + 64 + lane]        = f7 * y10;
            msg[160 + 128 + 64 + lane]  = f7 * y11;
            msg[160 + 256 + 64 + lane]  = f7 * y12;
            float f8 = y0 * mr[8];
            msg[160 + 96 + lane]        = mv0 * f8;
            msg[160 + 128 + 96 + lane]  = mv1 * f8;
            msg[160 + 256 + 96 + lane]  = mv2 * f8;
            __syncwarp();

            float* aggs = g_agg_s + (long)rcv * NSs;
            float* aggv = g_agg_v + (long)rcv * (NVv * 3);
            const float4* m4 = (const float4*)msg;
            #pragma unroll
            for (int gi = 0; gi < 5; gi++) {
                int g = lane + gi * 32;
                if (g < 136) {
                    float4 vv = m4[g];
                    float* p = (g < 40) ? (aggs + 4 * g) : (aggv + 4 * (g - 40));
                    asm volatile("red.global.add.v4.f32 [%0], {%1, %2, %3, %4};"
                                 :: "l"(p), "f"(vv.x), "f"(vv.y), "f"(vv.z), "f"(vv.w)
                                 : "memory");
                }
            }
            __syncwarp();
        }
    }
}

// ---------------- device gemm body, fp32x2 register-tiled, vectorized staging ----------------
// AMODE: 0 = row-major A (lda=K, K%4==0); 2 = ts on-the-fly (A=g_s1, K=256);
//        3 = tv on-the-fly (A=g_v1, K=128).
// CMODE: 0 = C = acc*scale; 2 = outS = acc + skip (+ smem tile + quantum);
//        3 = outV scatter = acc + skip.
template<int K, int N, int BM, int AMODE, int CMODE>
__device__ __forceinline__ void gemm_body(
    const float* __restrict__ A, const float* __restrict__ B,
    const float* __restrict__ skip, float* __restrict__ C, float scale,
    int bid, float* smg, const float* __restrict__ x_node,
    float* __restrict__ out0, const float* sq)
{
    constexpr int TX = N / 4;
    constexpr int TY = 256 / TX;
    constexpr int TM = BM / TY;
    constexpr int KP = K + 4;
    constexpr int NP = N + 4;
    float* sA = smg;             // BM*KP
    float* sB = sA + BM * KP;    // K*NP

    int t = threadIdx.x;
    int row0 = bid * BM;

    // ---- stage A (float4) ----
    if (AMODE == 0) {
        constexpr int K4 = K / 4;
        for (int i4 = t; i4 < BM * K4; i4 += 256) {
            int r = i4 / K4, k4 = i4 - r * K4;
            float4 v = *(const float4*)(A + (long)(row0 + r) * K + k4 * 4);
            *(float4*)(sA + r * KP + k4 * 4) = v;
        }
    } else if (AMODE == 2) {
        // rows = nodes; A row = g_s1[rr][0:64); replicate x4 with x_node factors
        for (int i4 = t; i4 < BM * 16; i4 += 256) {
            int r = i4 >> 4, c4 = i4 & 15;
            int rr = row0 + r;
            float4 v = *(const float4*)(A + (long)rr * 64 + c4 * 4);
            float4 xq = *(const float4*)(x_node + rr * 4);
            float xa[4] = {xq.x, xq.y, xq.z, xq.w};
            #pragma unroll
            for (int a = 0; a < 4; a++) {
                *(float4*)(sA + r * KP + a * 64 + c4 * 4) =
                    make_float4(xa[a] * v.x, xa[a] * v.y, xa[a] * v.z, xa[a] * v.w);
            }
        }
    } else {
        // AMODE 3: rows = (3n+ii); A row = g_v1[rr][0:32)
        for (int i4 = t; i4 < BM * 8; i4 += 256) {
            int r = i4 >> 3, c4 = i4 & 7;
            int rr = row0 + r;
            float4 v = *(const float4*)(A + (long)rr * 32 + c4 * 4);
            float4 xq = *(const float4*)(x_node + (rr / 3) * 4);
            float xa[4] = {xq.x, xq.y, xq.z, xq.w};
            #pragma unroll
            for (int a = 0; a < 4; a++) {
                *(float4*)(sA + r * KP + a * 32 + c4 * 4) =
                    make_float4(xa[a] * v.x, xa[a] * v.y, xa[a] * v.z, xa[a] * v.w);
            }
        }
    }
    // ---- stage B (float4) ----
    {
        constexpr int N4 = N / 4;
        for (int i4 = t; i4 < K * N4; i4 += 256) {
            int r = i4 / N4, c4 = i4 - r * N4;
            float4 v = *(const float4*)(B + (long)r * N + c4 * 4);
            *(float4*)(sB + r * NP + c4 * 4) = v;
        }
    }
    __syncthreads();

    int tx = t % TX, ty = t / TX;
    ull acc[TM][2];
    #pragma unroll
    for (int mi = 0; mi < TM; mi++) { acc[mi][0] = 0ull; acc[mi][1] = 0ull; }

    const float* aBase = sA + ty * TM * KP;
    const float* bBase = sB + 4 * tx;

    #pragma unroll 8
    for (int k = 0; k < K; k++) {
        ull b0 = lds64(bBase + k * NP);
        ull b1 = lds64(bBase + k * NP + 2);
        #pragma unroll
        for (int mi = 0; mi < TM; mi++) {
            ull ad = dup2(aBase[mi * KP + k]);
            acc[mi][0] = fma2(b0, ad, acc[mi][0]);
            acc[mi][1] = fma2(b1, ad, acc[mi][1]);
        }
    }

    if (CMODE == 0) {
        #pragma unroll
        for (int mi = 0; mi < TM; mi++) {
            int row = row0 + ty * TM + mi;
            float v0, v1, v2, v3;
            unpack2(acc[mi][0], v0, v1);
            unpack2(acc[mi][1], v2, v3);
            float4 o = make_float4(v0 * scale, v1 * scale, v2 * scale, v3 * scale);
            *(float4*)(C + (long)row * N + 4 * tx) = o;
        }
    } else if (CMODE == 3) {
        #pragma unroll
        for (int mi = 0; mi < TM; mi++) {
            int row = row0 + ty * TM + mi;
            float vv[4];
            unpack2(acc[mi][0], vv[0], vv[1]);
            unpack2(acc[mi][1], vv[2], vv[3]);
            int n = row / 3, ii = row - 3 * n;
            #pragma unroll
            for (int j = 0; j < 4; j++) {
                int c = 4 * tx + j;
                C[(long)n * 96 + c * 3 + ii] = vv[j] + skip[(long)n * 96 + c * 3 + ii];
            }
        }
    } else {
        // CMODE 2: outS + smem tile + fused quantum head
        float ov[TM][4];
        #pragma unroll
        for (int mi = 0; mi < TM; mi++) {
            int row = row0 + ty * TM + mi;
            float v0, v1, v2, v3;
            unpack2(acc[mi][0], v0, v1);
            unpack2(acc[mi][1], v2, v3);
            float4 sk = *(const float4*)(skip + (long)row * 64 + 4 * tx);
            ov[mi][0] = v0 + sk.x; ov[mi][1] = v1 + sk.y;
            ov[mi][2] = v2 + sk.z; ov[mi][3] = v3 + sk.w;
        }
        __syncthreads();                 // done reading sA; reuse as output tile
        float* sOut = smg;               // BM x 65
        #pragma unroll
        for (int mi = 0; mi < TM; mi++) {
            int r = ty * TM + mi;
            int row = row0 + r;
            *(float4*)(C + (long)row * 64 + 4 * tx) =
                make_float4(ov[mi][0], ov[mi][1], ov[mi][2], ov[mi][3]);
            sOut[r * 65 + 4 * tx]     = ov[mi][0];
            sOut[r * 65 + 4 * tx + 1] = ov[mi][1];
            sOut[r * 65 + 4 * tx + 2] = ov[mi][2];
            sOut[r * 65 + 4 * tx + 3] = ov[mi][3];
        }
        __syncthreads();

        const float* sWq = sq;
        const float* cw  = sq + 512;
        const float* sw_ = sq + 536;
        const float* sWo = sq + 560;
        float bo0 = sq[568];
        int w = t >> 5, lane = t & 31;

        #pragma unroll 1
        for (int pass = 0; pass < BM / 8; pass++) {
            int r = pass * 8 + w;
            int n = row0 + r;
            const float* srow = sOut + r * 65;
            float s_lo = srow[lane];
            float s_hi = srow[lane + 32];

            float frow[8];
            #pragma unroll
            for (int q = 0; q < 8; q++)
                frow[q] = s_lo * sWq[lane * 8 + q] + s_hi * sWq[(lane + 32) * 8 + q];
            #pragma unroll
            for (int q = 0; q < 8; q++) {
                #pragma unroll
                for (int off = 16; off > 0; off >>= 1)
                    frow[q] += __shfl_xor_sync(0xffffffffu, frow[q], off);
            }

            float cs[8], sn[8];
            #pragma unroll
            for (int q = 0; q < 8; q++) {
                float a = 0.5f * frow[q];
                __sincosf(a, &sn[q], &cs[q]);
            }
            float lf = 1.f;
            #pragma unroll
            for (int j = 0; j < 5; j++) {
                int q = 4 - j;
                lf *= ((lane >> j) & 1) ? sn[q] : cs[q];
            }
            float amp[8];
            #pragma unroll
            for (int l = 0; l < 8; l++) {
                float f = lf;
                f *= (l & 4) ? sn[5] : cs[5];
                f *= (l & 2) ? sn[6] : cs[6];
                f *= (l & 1) ? sn[7] : cs[7];
                amp[l] = f;
            }

            #pragma unroll
            for (int L = 0; L < 3; L++) {
                #pragma unroll
                for (int q = 0; q < 8; q++) {
                    float c = cw[L * 8 + q], s = sw_[L * 8 + q];
                    const int b = 7 - q;
                    if (b >= 3) {
                        const int m = 1 << (b - 3);
                        int bit = (lane >> (b - 3)) & 1;
                        #pragma unroll
                        for (int l = 0; l < 8; l++) {
                            float p = __shfl_xor_sync(0xffffffffu, amp[l], m);
                            amp[l] = bit ? fmaf(s, p, c * amp[l]) : (c * amp[l] - s * p);
                        }
                    } else {
                        const int tm = 1 << b;
                        #pragma unroll
                        for (int l = 0; l < 8; l++) {
                            if (!(l & tm)) {
                                float a0 = amp[l], a1 = amp[l | tm];
                                amp[l]      = c * a0 - s * a1;
                                amp[l | tm] = fmaf(s, a0, c * a1);
                            }
                        }
                    }
                }
                #pragma unroll
                for (int q = 0; q < 8; q++) {
                    const int bc = 7 - q;
                    const int bt = 7 - ((q + 1) & 7);
                    if (bt >= 3) {
                        const int m = 1 << (bt - 3);
                        #pragma unroll
                        for (int l = 0; l < 8; l++) {
                            float p = __shfl_xor_sync(0xffffffffu, amp[l], m);
                            int ctrl = (bc >= 3) ? ((lane >> (bc - 3)) & 1) : ((l >> bc) & 1);
                            amp[l] = ctrl ? p : amp[l];
                        }
                    } else {
                        const int tm = 1 << bt;
                        if (bc >= 3) {
                            int ctrl = (lane >> (bc - 3)) & 1;
                            #pragma unroll
                            for (int l = 0; l < 8; l++) {
                                if (!(l & tm)) {
                                    float a = amp[l], bb = amp[l | tm];
                                    amp[l]      = ctrl ? bb : a;
                                    amp[l | tm] = ctrl ? a : bb;
                                }
                            }
                        } else {
                            #pragma unroll
                            for (int l = 0; l < 8; l++) {
                                if (!(l & tm) && ((l >> bc) & 1)) {
                                    float tmp = amp[l];
                                    amp[l] = amp[l | tm];
                                    amp[l | tm] = tmp;
                                }
                            }
                        }
                    }
                }
            }

            float tsum = 0.f, tb0 = 0.f, tb1 = 0.f, tb2 = 0.f;
            #pragma unroll
            for (int l = 0; l < 8; l++) {
                float p = amp[l] * amp[l];
                tsum += p;
                tb0 += (l & 1) ? -p : p;
                tb1 += (l & 2) ? -p : p;
                tb2 += (l & 4) ? -p : p;
            }
            float lanesum = 0.f;
            #pragma unroll
            for (int q = 0; q < 5; q++) {
                float sgn = ((lane >> (4 - q)) & 1) ? -1.f : 1.f;
                lanesum = fmaf(sgn * sWo[q], 1.f, lanesum);
            }
            float op = sWo[7] * tb0 + sWo[6] * tb1 + sWo[5] * tb2 + tsum * lanesum;
            #pragma unroll
            for (int o = 16; o > 0; o >>= 1)
                op += __shfl_xor_sync(0xffffffffu, op, o);
            if (lane == 0) out0[n] = op + bo0;
        }
    }
}

// nodeA smem: max( 64*164+160*68 = 21376 , 128*132+128*36 = 21504 ) = 21504 floats
// nodeB smem: max( 32*260+256*68 = 25728 , 128*132+128*36 = 21504 ) + 576(sq) = 26304 floats
#define NODEB_SQ_OFF 25728

// ---------------- nodeA: both first-stage GEMMs in one launch ----------------
__global__ void __launch_bounds__(256, 2) nodeA_kernel(
    const float* __restrict__ Wd0, const float* __restrict__ Wd1)
{
    extern __shared__ float smg[];
    const float inv16 = 1.0f / 16.0f;
    if (blockIdx.x < 128)
        gemm_body<160, 64, 64, 0, 0>(g_agg_s, Wd0, nullptr, g_s1, inv16,
                                     blockIdx.x, smg, nullptr, nullptr, nullptr);
    else
        gemm_body<128, 32, 128, 0, 0>(g_agg_v, Wd1, nullptr, g_v1, inv16,
                                      blockIdx.x - 128, smg, nullptr, nullptr, nullptr);
}

// ---------------- nodeB: both second-stage GEMMs + fused quantum head ----------------
__global__ void __launch_bounds__(256, 2) nodeB_kernel(
    const float* __restrict__ Wt0, const float* __restrict__ Wt1,
    const float* __restrict__ x_node,
    const float* __restrict__ Wq, const float* __restrict__ wqml,
    const float* __restrict__ Wo, const float* __restrict__ bo,
    float* __restrict__ out0, float* __restrict__ outS, float* __restrict__ outV)
{
    extern __shared__ float smg[];
    float* sq = smg + NODEB_SQ_OFF;
    int t = threadIdx.x;
    for (int i = t; i < 512; i += 256) sq[i] = Wq[i];
    if (t < 24) {
        float ang = 0.5f * wqml[t];
        sq[512 + t] = cosf(ang);
        sq[536 + t] = sinf(ang);
    }
    if (t < 8)  sq[560 + t] = Wo[t];
    if (t == 0) sq[568] = bo[0];
    __syncthreads();

    if (blockIdx.x < 256)
        gemm_body<256, 64, 32, 2, 2>(g_s1, Wt0, g_skip_s, outS, 1.0f,
                                     blockIdx.x, smg, x_node, out0, sq);
    else
        gemm_body<128, 32, 128, 3, 3>(g_v1, Wt1, g_skip_v, outV, 1.0f,
                                      blockIdx.x - 256, smg, x_node, nullptr, nullptr);
}

// ---------------- launch ----------------
extern "C" void kernel_launch(void* const* d_in, const int* in_sizes, int n_in,
                              void* d_out, int out_size) {
    const float* s_in     = (const float*)d_in[0];
    const float* v_in     = (const float*)d_in[1];
    const float* x_node   = (const float*)d_in[2];
    const float* radial   = (const float*)d_in[3];
    const float* Y0       = (const float*)d_in[4];
    const float* Y1       = (const float*)d_in[5];
    const int*   species  = (const int*)d_in[6];
    const int*   senders  = (const int*)d_in[7];
    const int*   receivers= (const int*)d_in[8];
    const float* Wskip0   = (const float*)d_in[9];
    const float* Wskip1   = (const float*)d_in[10];
    const float* Wu0      = (const float*)d_in[11];
    const float* Wu1      = (const float*)d_in[12];
    const float* Wm1      = (const float*)d_in[13];
    const float* Wm2      = (const float*)d_in[14];
    const float* Wm3      = (const float*)d_in[15];
    const float* Wd0      = (const float*)d_in[16];
    const float* Wd1      = (const float*)d_in[17];
    const float* Wt0      = (const float*)d_in[18];
    const float* Wt1      = (const float*)d_in[19];
    const float* Wq       = (const float*)d_in[20];
    const float* wqml     = (const float*)d_in[21];
    const float* Wo       = (const float*)d_in[22];
    const float* bo       = (const float*)d_in[23];

    float* out0 = (float*)d_out;
    float* outS = out0 + Nn;
    float* outV = outS + Nn * C0;

    static bool attr_done = false;
    size_t smem_pre   = (4096 + 1024 + 16384 + 4096 + 8 * 160) * sizeof(float);
    size_t smem_edge  = (512 + 4096 + 18432 + EW * 1568) * sizeof(float);
    size_t smem_nodeA = 21504 * sizeof(float);              // 86 KB -> 2 blocks/SM
    size_t smem_nodeB = (NODEB_SQ_OFF + 576) * sizeof(float); // ~103 KB -> 2 blocks/SM
    if (!attr_done) {
        cudaFuncSetAttribute(node_pre_kernel, cudaFuncAttributeMaxDynamicSharedMemorySize, (int)smem_pre);
        cudaFuncSetAttribute(edge_kernel,     cudaFuncAttributeMaxDynamicSharedMemorySize, (int)smem_edge);
        cudaFuncSetAttribute(nodeA_kernel,    cudaFuncAttributeMaxDynamicSharedMemorySize, (int)smem_nodeA);
        cudaFuncSetAttribute(nodeB_kernel,    cudaFuncAttributeMaxDynamicSharedMemorySize, (int)smem_nodeB);
        attr_done = true;
    }

    zero_agg_kernel<<<1024, 256>>>();
    node_pre_kernel<<<296, 256, smem_pre>>>(s_in, v_in, species, Wskip0, Wskip1, Wu0, Wu1);
    edge_kernel<<<148, 32 * EW, smem_edge>>>(radial, Y0, Y1, senders, receivers, Wm1, Wm2, Wm3);
    nodeA_kernel<<<320, 256, smem_nodeA>>>(Wd0, Wd1);
    nodeB_kernel<<<448, 256, smem_nodeB>>>(Wt0, Wt1, x_node, Wq, wqml, Wo, bo, out0, outS, outV);
}

// round 9
// speedup vs baseline: 1.2104x; 1.0117x over previous
#include <cuda_runtime.h>
#include <math.h>

#define Nn 8192
#define Ee 131072
#define C0 64
#define C1 32
#define NSs 160     // 2*C0 + C1
#define NVv 128     // C0 + 2*C1
#define EPB 8       // edges per warp batch (edge kernel)
#define NPAIR 4     // EPB/2
#define EW 16       // warps per edge block

typedef unsigned long long ull;

// ---------------- static device scratch ----------------
__device__ float g_s[Nn * C0];
__device__ float g_v[Nn * C1 * 3];
__device__ float g_skip_s[Nn * C0];
__device__ float g_skip_v[Nn * C1 * 3];
__device__ float g_agg_s[Nn * NSs];
__device__ float g_agg_v[Nn * 3 * NVv];  // [n][ii][c]  (component-major)

__device__ __forceinline__ float silu_f(float x) {
    return __fdividef(x, 1.0f + __expf(-x));
}

// packed fp32x2 helpers (sm_100a): bit-exact dual fp32 FMA
__device__ __forceinline__ ull pack2(float x, float y) {
    ull r; asm("mov.b64 %0, {%1, %2};" : "=l"(r) : "f"(x), "f"(y)); return r;
}
__device__ __forceinline__ void unpack2(ull v, float& x, float& y) {
    asm("mov.b64 {%0, %1}, %2;" : "=f"(x), "=f"(y) : "l"(v));
}
__device__ __forceinline__ ull fma2(ull a, ull b, ull c) {
    ull d; asm("fma.rn.f32x2 %0, %1, %2, %3;" : "=l"(d) : "l"(a), "l"(b), "l"(c)); return d;
}
__device__ __forceinline__ ull dup2(float x) { return pack2(x, x); }
__device__ __forceinline__ ull lds64(const float* p) { return *(const ull*)p; }

// ---------------- kernel 1: node pre (zero agg + Wu0/Wu1 + skips) ----------------
__global__ void __launch_bounds__(256) node_pre_kernel(
    const float* __restrict__ s_in, const float* __restrict__ v_in,
    const int* __restrict__ species,
    const float* __restrict__ Wskip0, const float* __restrict__ Wskip1,
    const float* __restrict__ Wu0, const float* __restrict__ Wu1)
{
    extern __shared__ float sm[];
    float* sWu0 = sm;                  // 4096
    float* sWu1 = sWu0 + 4096;         // 1024
    float* sWs0 = sWu1 + 1024;         // 16384
    float* sWs1 = sWs0 + 16384;        // 4096
    float* bufs = sWs1 + 4096;         // 8 warps * 160

    int tid = threadIdx.x;

    // zero aggregation buffers (kernel boundary orders this before edge_kernel)
    {
        int gt = blockIdx.x * 256 + tid;
        int gstride = gridDim.x * 256;
        float4 z4 = make_float4(0.f, 0.f, 0.f, 0.f);
        float4* az = (float4*)g_agg_s;
        for (int j = gt; j < Nn * NSs / 4; j += gstride) az[j] = z4;
        float4* bz = (float4*)g_agg_v;
        for (int j = gt; j < Nn * 3 * NVv / 4; j += gstride) bz[j] = z4;
    }

    for (int i = tid; i < 4096;  i += blockDim.x) sWu0[i] = Wu0[i];
    for (int i = tid; i < 1024;  i += blockDim.x) sWu1[i] = Wu1[i];
    for (int i = tid; i < 16384; i += blockDim.x) sWs0[i] = Wskip0[i];
    for (int i = tid; i < 4096;  i += blockDim.x) sWs1[i] = Wskip1[i];
    __syncthreads();

    int w = tid >> 5, lane = tid & 31;
    float* sb = bufs + w * 160;
    float* vb = sb + 64;
    int warpsTotal = gridDim.x * 8;

    for (int n = blockIdx.x * 8 + w; n < Nn; n += warpsTotal) {
        sb[lane]      = s_in[n * 64 + lane];
        sb[lane + 32] = s_in[n * 64 + lane + 32];
        vb[lane]      = v_in[n * 96 + lane];
        vb[lane + 32] = v_in[n * 96 + lane + 32];
        vb[lane + 64] = v_in[n * 96 + lane + 64];
        __syncwarp();
        int sp = species[n];
        const float* Ws0 = sWs0 + sp * 4096;
        const float* Ws1 = sWs1 + sp * 1024;

        float a0 = 0.f, a1 = 0.f, b0 = 0.f, b1 = 0.f;
        #pragma unroll 8
        for (int c = 0; c < 64; c++) {
            float x = sb[c];
            a0 = fmaf(x, sWu0[c * 64 + lane],      a0);
            a1 = fmaf(x, sWu0[c * 64 + lane + 32], a1);
            b0 = fmaf(x, Ws0[c * 64 + lane],       b0);
            b1 = fmaf(x, Ws0[c * 64 + lane + 32],  b1);
        }
        g_s[n * 64 + lane]      = a0;
        g_s[n * 64 + lane + 32] = a1;
        g_skip_s[n * 64 + lane]      = b0;
        g_skip_s[n * 64 + lane + 32] = b1;

        float u0 = 0.f, u1 = 0.f, u2 = 0.f, k0 = 0.f, k1 = 0.f, k2 = 0.f;
        #pragma unroll 8
        for (int c = 0; c < 32; c++) {
            float wu = sWu1[c * 32 + lane];
            float wk = Ws1[c * 32 + lane];
            float x0 = vb[c * 3], x1 = vb[c * 3 + 1], x2 = vb[c * 3 + 2];
            u0 = fmaf(x0, wu, u0); u1 = fmaf(x1, wu, u1); u2 = fmaf(x2, wu, u2);
            k0 = fmaf(x0, wk, k0); k1 = fmaf(x1, wk, k1); k2 = fmaf(x2, wk, k2);
        }
        g_v[n * 96 + lane * 3]     = u0;
        g_v[n * 96 + lane * 3 + 1] = u1;
        g_v[n * 96 + lane * 3 + 2] = u2;
        g_skip_v[n * 96 + lane * 3]     = k0;
        g_skip_v[n * 96 + lane * 3 + 1] = k1;
        g_skip_v[n * 96 + lane * 3 + 2] = k2;
        __syncwarp();
    }
}

// ---------------- kernel 2: fused edge MLP (fp32x2 packed) + scatter ----------------
// msg layout: [0:160) scalar channels; [160:544) vector part [ii][c] (c in 0..127)
__global__ void __launch_bounds__(32 * EW) edge_kernel(
    const float* __restrict__ radial, const float* __restrict__ Y0,
    const float* __restrict__ Y1,
    const int* __restrict__ senders, const int* __restrict__ receivers,
    const float* __restrict__ Wm1, const float* __restrict__ Wm2,
    const float* __restrict__ Wm3)
{
    extern __shared__ float sm[];
    float* sWm1 = sm;                 // 512
    float* sWm2 = sWm1 + 512;         // 4096
    float* sWm3 = sWm2 + 4096;        // 18432
    float* wb   = sWm3 + 18432;

    int tid = threadIdx.x, w = tid >> 5, lane = tid & 31;
    for (int i = tid; i < 512;   i += blockDim.x) sWm1[i] = Wm1[i];
    for (int i = tid; i < 4096;  i += blockDim.x) sWm2[i] = Wm2[i];
    for (int i = tid; i < 18432; i += blockDim.x) sWm3[i] = Wm3[i];
    __syncthreads();

    const int perW = 512 + 512 + 544;   // h1(pairs) + h2(pairs) + msg
    float* h1f = wb + w * perW;
    float* h2f = h1f + 512;
    float* msg = h2f + 512;
    ull* h1u = (ull*)h1f;
    ull* h2u = (ull*)h2f;

    int nwarps = gridDim.x * EW;
    int gw = blockIdx.x * EW + w;
    const float inv_s3 = 0.57735026918962576f;

    for (int e0 = gw * EPB; e0 < Ee; e0 += nwarps * EPB) {
        // ---- layer 1 ----
        #pragma unroll
        for (int p = 0; p < NPAIR; p++) {
            float sv[2][2];
            #pragma unroll
            for (int hh = 0; hh < 2; hh++) {
                int e = e0 + 2 * p + hh;
                float rv = (lane < 8) ? radial[e * 8 + lane] : 0.f;
                float a0 = 0.f, a1 = 0.f;
                #pragma unroll
                for (int k = 0; k < 8; k++) {
                    float rk = __shfl_sync(0xffffffffu, rv, k);
                    a0 = fmaf(rk, sWm1[k * 64 + lane],      a0);
                    a1 = fmaf(rk, sWm1[k * 64 + lane + 32], a1);
                }
                sv[hh][0] = silu_f(a0);
                sv[hh][1] = silu_f(a1);
            }
            h1u[p * 64 + lane]      = pack2(sv[0][0], sv[1][0]);
            h1u[p * 64 + lane + 32] = pack2(sv[0][1], sv[1][1]);
        }
        __syncwarp();

        // ---- layer 2 ----
        {
            ull acc0[NPAIR], acc1[NPAIR];
            #pragma unroll
            for (int p = 0; p < NPAIR; p++) { acc0[p] = 0ull; acc1[p] = 0ull; }
            for (int k = 0; k < 64; k++) {
                float w0 = sWm2[k * 64 + lane];
                float w1 = sWm2[k * 64 + lane + 32];
                ull w0p = dup2(w0);
                ull w1p = dup2(w1);
                #pragma unroll
                for (int p = 0; p < NPAIR; p++) {
                    ull hp = h1u[p * 64 + k];
                    acc0[p] = fma2(hp, w0p, acc0[p]);
                    acc1[p] = fma2(hp, w1p, acc1[p]);
                }
            }
            #pragma unroll
            for (int p = 0; p < NPAIR; p++) {
                float x, y;
                unpack2(acc0[p], x, y);
                h2u[p * 64 + lane] = pack2(silu_f(x), silu_f(y));
                unpack2(acc1[p], x, y);
                h2u[p * 64 + lane + 32] = pack2(silu_f(x), silu_f(y));
            }
        }
        __syncwarp();

        // ---- layer 3 ----
        ull m2[NPAIR * 9];
        #pragma unroll
        for (int i = 0; i < NPAIR * 9; i++) m2[i] = 0ull;

        for (int k = 0; k < 64; k++) {
            ull hp[NPAIR];
            #pragma unroll
            for (int p = 0; p < NPAIR; p++) hp[p] = h2u[p * 64 + k];
            #pragma unroll
            for (int r = 0; r < 9; r++) {
                float wv = sWm3[k * 288 + lane + 32 * r];
                ull wp = dup2(wv);
                #pragma unroll
                for (int p = 0; p < NPAIR; p++)
                    m2[p * 9 + r] = fma2(hp[p], wp, m2[p * 9 + r]);
            }
        }

        // ---- messages + scatter ----
        #pragma unroll
        for (int t = 0; t < EPB; t++) {
            int pp = t >> 1, hh = t & 1;
            float mr[9];
            #pragma unroll
            for (int r = 0; r < 9; r++) {
                float lo, hi;
                unpack2(m2[pp * 9 + r], lo, hi);
                mr[r] = hh ? hi : lo;
            }
            int e = e0 + t;
            int snd = senders[e];
            int rcv = receivers[e];
            float m0  = g_s[snd * 64 + lane];
            float m1  = g_s[snd * 64 + lane + 32];
            float mv0 = g_v[snd * 96 + lane * 3];
            float mv1 = g_v[snd * 96 + lane * 3 + 1];
            float mv2 = g_v[snd * 96 + lane * 3 + 2];
            float y0  = Y0[e];
            float y10 = Y1[e * 3], y11 = Y1[e * 3 + 1], y12 = Y1[e * 3 + 2];
            float dot = (mv0 * y10 + mv1 * y11 + mv2 * y12) * inv_s3;

            msg[lane]       = m0 * mr[0];
            msg[32 + lane]  = m1 * mr[1];
            msg[64 + lane]  = m0 * y0 * mr[2];
            msg[96 + lane]  = m1 * y0 * mr[3];
            msg[128 + lane] = dot * mr[4];
            float vv5 = mr[5];
            msg[160 + lane]       = mv0 * vv5;
            msg[160 + 128 + lane] = mv1 * vv5;
            msg[160 + 256 + lane] = mv2 * vv5;
            float f6 = m0 * mr[6];
            msg[160 + 32 + lane]        = f6 * y10;
            msg[160 + 128 + 32 + lane]  = f6 * y11;
            msg[160 + 256 + 32 + lane]  = f6 * y12;
            float f7 = m1 * mr[7];
            msg[160 + 64 + lane]        = f7 * y10;
            msg[160 + 128 + 64 + lane]  = f7 * y11;
            msg[160 + 256 + 64 + lane]  = f7 * y12;
            float f8 = y0 * mr[8];
            msg[160 + 96 + lane]        = mv0 * f8;
            msg[160 + 128 + 96 + lane]  = mv1 * f8;
            msg[160 + 256 + 96 + lane]  = mv2 * f8;
            __syncwarp();

            float* aggs = g_agg_s + (long)rcv * NSs;
            float* aggv = g_agg_v + (long)rcv * (NVv * 3);
            const float4* m4 = (const float4*)msg;
            #pragma unroll
            for (int gi = 0; gi < 5; gi++) {
                int g = lane + gi * 32;
                if (g < 136) {
                    float4 vv = m4[g];
                    float* p = (g < 40) ? (aggs + 4 * g) : (aggv + 4 * (g - 40));
                    asm volatile("red.global.add.v4.f32 [%0], {%1, %2, %3, %4};"
                                 :: "l"(p), "f"(vv.x), "f"(vv.y), "f"(vv.z), "f"(vv.w)
                                 : "memory");
                }
            }
            __syncwarp();
        }
    }
}

// ---------------- node_kernel: full node path in one launch ----------------
// smem (floats): region0 [0, 21504) multi-use; s1s/v1s [21504, 26112); sq [26112, 26688)
#define S1OFF  21504
#define SQOFF  26112
#define NODE_SMEM_FLOATS 26688

__device__ void quantum_rows(const float* sOut, const float* sq, int row0,
                             int nrows, float* out0)
{
    int t = threadIdx.x;
    const float* sWq = sq;
    const float* cw  = sq + 512;
    const float* sw_ = sq + 536;
    const float* sWo = sq + 560;
    float bo0 = sq[568];
    int w = t >> 5, lane = t & 31;

    #pragma unroll 1
    for (int pass = 0; pass < nrows / 8; pass++) {
        int r = pass * 8 + w;
        int n = row0 + r;
        const float* srow = sOut + r * 65;
        float s_lo = srow[lane];
        float s_hi = srow[lane + 32];

        float frow[8];
        #pragma unroll
        for (int q = 0; q < 8; q++)
            frow[q] = s_lo * sWq[lane * 8 + q] + s_hi * sWq[(lane + 32) * 8 + q];
        #pragma unroll
        for (int q = 0; q < 8; q++) {
            #pragma unroll
            for (int off = 16; off > 0; off >>= 1)
                frow[q] += __shfl_xor_sync(0xffffffffu, frow[q], off);
        }

        float cs[8], sn[8];
        #pragma unroll
        for (int q = 0; q < 8; q++) {
            float a = 0.5f * frow[q];
            __sincosf(a, &sn[q], &cs[q]);
        }
        float lf = 1.f;
        #pragma unroll
        for (int j = 0; j < 5; j++) {
            int q = 4 - j;
            lf *= ((lane >> j) & 1) ? sn[q] : cs[q];
        }
        float amp[8];
        #pragma unroll
        for (int l = 0; l < 8; l++) {
            float f = lf;
            f *= (l & 4) ? sn[5] : cs[5];
            f *= (l & 2) ? sn[6] : cs[6];
            f *= (l & 1) ? sn[7] : cs[7];
            amp[l] = f;
        }

        #pragma unroll
        for (int L = 0; L < 3; L++) {
            #pragma unroll
            for (int q = 0; q < 8; q++) {
                float c = cw[L * 8 + q], s = sw_[L * 8 + q];
                const int b = 7 - q;
                if (b >= 3) {
                    const int m = 1 << (b - 3);
                    int bit = (lane >> (b - 3)) & 1;
                    #pragma unroll
                    for (int l = 0; l < 8; l++) {
                        float p = __shfl_xor_sync(0xffffffffu, amp[l], m);
                        amp[l] = bit ? fmaf(s, p, c * amp[l]) : (c * amp[l] - s * p);
                    }
                } else {
                    const int tm = 1 << b;
                    #pragma unroll
                    for (int l = 0; l < 8; l++) {
                        if (!(l & tm)) {
                            float a0 = amp[l], a1 = amp[l | tm];
                            amp[l]      = c * a0 - s * a1;
                            amp[l | tm] = fmaf(s, a0, c * a1);
                        }
                    }
                }
            }
            #pragma unroll
            for (int q = 0; q < 8; q++) {
                const int bc = 7 - q;
                const int bt = 7 - ((q + 1) & 7);
                if (bt >= 3) {
                    const int m = 1 << (bt - 3);
                    #pragma unroll
                    for (int l = 0; l < 8; l++) {
                        float p = __shfl_xor_sync(0xffffffffu, amp[l], m);
                        int ctrl = (bc >= 3) ? ((lane >> (bc - 3)) & 1) : ((l >> bc) & 1);
                        amp[l] = ctrl ? p : amp[l];
                    }
                } else {
                    const int tm = 1 << bt;
                    if (bc >= 3) {
                        int ctrl = (lane >> (bc - 3)) & 1;
                        #pragma unroll
                        for (int l = 0; l < 8; l++) {
                            if (!(l & tm)) {
                                float a = amp[l], bb = amp[l | tm];
                                amp[l]      = ctrl ? bb : a;
                                amp[l | tm] = ctrl ? a : bb;
                            }
                        }
                    } else {
                        #pragma unroll
                        for (int l = 0; l < 8; l++) {
                            if (!(l & tm) && ((l >> bc) & 1)) {
                                float tmp = amp[l];
                                amp[l] = amp[l | tm];
                                amp[l | tm] = tmp;
                            }
                        }
                    }
                }
            }
        }

        float tsum = 0.f, tb0 = 0.f, tb1 = 0.f, tb2 = 0.f;
        #pragma unroll
        for (int l = 0; l < 8; l++) {
            float p = amp[l] * amp[l];
            tsum += p;
            tb0 += (l & 1) ? -p : p;
            tb1 += (l & 2) ? -p : p;
            tb2 += (l & 4) ? -p : p;
        }
        float lanesum = 0.f;
        #pragma unroll
        for (int q = 0; q < 5; q++) {
            float sgn = ((lane >> (4 - q)) & 1) ? -1.f : 1.f;
            lanesum = fmaf(sgn * sWo[q], 1.f, lanesum);
        }
        float op = sWo[7] * tb0 + sWo[6] * tb1 + sWo[5] * tb2 + tsum * lanesum;
        #pragma unroll
        for (int o = 16; o > 0; o >>= 1)
            op += __shfl_xor_sync(0xffffffffu, op, o);
        if (lane == 0) out0[n] = op + bo0;
    }
}

__global__ void __launch_bounds__(256, 2) node_kernel(
    const float* __restrict__ Wd0, const float* __restrict__ Wd1,
    const float* __restrict__ Wt0, const float* __restrict__ Wt1,
    const float* __restrict__ x_node,
    const float* __restrict__ Wq, const float* __restrict__ wqml,
    const float* __restrict__ Wo, const float* __restrict__ bo,
    float* __restrict__ out0, float* __restrict__ outS, float* __restrict__ outV)
{
    extern __shared__ float smg[];
    float* sq = smg + SQOFF;
    int t = threadIdx.x;
    const float inv16 = 1.0f / 16.0f;

    for (int i = t; i < 512; i += 256) sq[i] = Wq[i];
    if (t < 24) {
        float ang = 0.5f * wqml[t];
        sq[512 + t] = cosf(ang);
        sq[536 + t] = sinf(ang);
    }
    if (t < 8)  sq[560 + t] = Wo[t];
    if (t == 0) sq[568] = bo[0];

    if (blockIdx.x < 128) {
        // =================== s branch: 64 nodes ===================
        int row0 = blockIdx.x * 64;
        float* sA1 = smg;              // 64 x 164
        float* sB1 = smg + 10496;      // 160 x 68
        float* s1s = smg + S1OFF;      // 64 x 68

        for (int i4 = t; i4 < 64 * 40; i4 += 256) {
            int r = i4 / 40, c4 = i4 - r * 40;
            *(float4*)(sA1 + r * 164 + c4 * 4) =
                *(const float4*)(g_agg_s + (long)(row0 + r) * 160 + c4 * 4);
        }
        for (int i4 = t; i4 < 160 * 16; i4 += 256) {
            int r = i4 >> 4, c4 = i4 & 15;
            *(float4*)(sB1 + r * 68 + c4 * 4) = *(const float4*)(Wd0 + r * 64 + c4 * 4);
        }
        __syncthreads();

        int tx = t & 15, ty = t >> 4;   // TX=16, TY=16, TM=4
        {
            ull acc[4][2];
            #pragma unroll
            for (int mi = 0; mi < 4; mi++) { acc[mi][0] = 0ull; acc[mi][1] = 0ull; }
            const float* aB = sA1 + ty * 4 * 164;
            const float* bB = sB1 + 4 * tx;
            #pragma unroll 4
            for (int k = 0; k < 160; k++) {
                ull b0 = lds64(bB + k * 68);
                ull b1 = lds64(bB + k * 68 + 2);
                #pragma unroll
                for (int mi = 0; mi < 4; mi++) {
                    ull ad = dup2(aB[mi * 164 + k]);
                    acc[mi][0] = fma2(b0, ad, acc[mi][0]);
                    acc[mi][1] = fma2(b1, ad, acc[mi][1]);
                }
            }
            #pragma unroll
            for (int mi = 0; mi < 4; mi++) {
                float v0, v1, v2, v3;
                unpack2(acc[mi][0], v0, v1);
                unpack2(acc[mi][1], v2, v3);
                *(float4*)(s1s + (ty * 4 + mi) * 68 + 4 * tx) =
                    make_float4(v0 * inv16, v1 * inv16, v2 * inv16, v3 * inv16);
            }
        }
        __syncthreads();

        // phase 2: outS = (x (x) s1) @ Wt0 + skip; expansion fused into mainloop
        float* sB2 = smg;              // 256 x 68
        for (int i4 = t; i4 < 256 * 16; i4 += 256) {
            int r = i4 >> 4, c4 = i4 & 15;
            *(float4*)(sB2 + r * 68 + c4 * 4) = *(const float4*)(Wt0 + r * 64 + c4 * 4);
        }
        float xr[4][4];
        #pragma unroll
        for (int mi = 0; mi < 4; mi++) {
            float4 xq = *(const float4*)(x_node + (row0 + ty * 4 + mi) * 4);
            xr[mi][0] = xq.x; xr[mi][1] = xq.y; xr[mi][2] = xq.z; xr[mi][3] = xq.w;
        }
        __syncthreads();

        float ov[4][4];
        {
            ull acc[4][2];
            #pragma unroll
            for (int mi = 0; mi < 4; mi++) { acc[mi][0] = 0ull; acc[mi][1] = 0ull; }
            const float* bB = sB2 + 4 * tx;
            const float* s1B = s1s + ty * 4 * 68;
            #pragma unroll 1
            for (int a = 0; a < 4; a++) {
                const float* bA = bB + a * 64 * 68;
                #pragma unroll 4
                for (int c = 0; c < 64; c++) {
                    ull b0 = lds64(bA + c * 68);
                    ull b1 = lds64(bA + c * 68 + 2);
                    #pragma unroll
                    for (int mi = 0; mi < 4; mi++) {
                        float sv = s1B[mi * 68 + c];
                        ull ad = dup2(xr[mi][a] * sv);
                        acc[mi][0] = fma2(b0, ad, acc[mi][0]);
                        acc[mi][1] = fma2(b1, ad, acc[mi][1]);
                    }
                }
            }
            #pragma unroll
            for (int mi = 0; mi < 4; mi++) {
                int row = row0 + ty * 4 + mi;
                float v0, v1, v2, v3;
                unpack2(acc[mi][0], v0, v1);
                unpack2(acc[mi][1], v2, v3);
                float4 sk = *(const float4*)(g_skip_s + (long)row * 64 + 4 * tx);
                ov[mi][0] = v0 + sk.x; ov[mi][1] = v1 + sk.y;
                ov[mi][2] = v2 + sk.z; ov[mi][3] = v3 + sk.w;
            }
        }
        __syncthreads();                 // sB2 dead
        float* sOut = smg;               // 64 x 65
        #pragma unroll
        for (int mi = 0; mi < 4; mi++) {
            int r = ty * 4 + mi;
            int row = row0 + r;
            *(float4*)(outS + (long)row * 64 + 4 * tx) =
                make_float4(ov[mi][0], ov[mi][1], ov[mi][2], ov[mi][3]);
            sOut[r * 65 + 4 * tx]     = ov[mi][0];
            sOut[r * 65 + 4 * tx + 1] = ov[mi][1];
            sOut[r * 65 + 4 * tx + 2] = ov[mi][2];
            sOut[r * 65 + 4 * tx + 3] = ov[mi][3];
        }
        __syncthreads();

        quantum_rows(sOut, sq, row0, 64, out0);
    } else {
        // =================== v branch: 128 rows of (3n+ii) ===================
        int row0 = (blockIdx.x - 128) * 128;
        float* sA  = smg;              // 128 x 132
        float* sB1 = smg + 16896;      // 128 x 36
        float* v1s = smg + S1OFF;      // 128 x 36

        for (int i4 = t; i4 < 128 * 32; i4 += 256) {
            int r = i4 >> 5, c4 = i4 & 31;
            *(float4*)(sA + r * 132 + c4 * 4) =
                *(const float4*)(g_agg_v + (long)(row0 + r) * 128 + c4 * 4);
        }
        for (int i4 = t; i4 < 128 * 8; i4 += 256) {
            int r = i4 >> 3, c4 = i4 & 7;
            *(float4*)(sB1 + r * 36 + c4 * 4) = *(const float4*)(Wd1 + r * 32 + c4 * 4);
        }
        __syncthreads();

        int tx = t & 7, ty = t >> 3;    // TX=8, TY=32, TM=4
        {
            ull acc[4][2];
            #pragma unroll
            for (int mi = 0; mi < 4; mi++) { acc[mi][0] = 0ull; acc[mi][1] = 0ull; }
            const float* aB = sA + ty * 4 * 132;
            const float* bB = sB1 + 4 * tx;
            #pragma unroll 4
            for (int k = 0; k < 128; k++) {
                ull b0 = lds64(bB + k * 36);
                ull b1 = lds64(bB + k * 36 + 2);
                #pragma unroll
                for (int mi = 0; mi < 4; mi++) {
                    ull ad = dup2(aB[mi * 132 + k]);
                    acc[mi][0] = fma2(b0, ad, acc[mi][0]);
                    acc[mi][1] = fma2(b1, ad, acc[mi][1]);
                }
            }
            #pragma unroll
            for (int mi = 0; mi < 4; mi++) {
                float v0, v1, v2, v3;
                unpack2(acc[mi][0], v0, v1);
                unpack2(acc[mi][1], v2, v3);
                *(float4*)(v1s + (ty * 4 + mi) * 36 + 4 * tx) =
                    make_float4(v0 * inv16, v1 * inv16, v2 * inv16, v3 * inv16);
            }
        }
        __syncthreads();

        float* sB2 = smg;              // 128 x 36
        for (int i4 = t; i4 < 128 * 8; i4 += 256) {
            int r = i4 >> 3, c4 = i4 & 7;
            *(float4*)(sB2 + r * 36 + c4 * 4) = *(const float4*)(Wt1 + r * 32 + c4 * 4);
        }
        float xr[4][4];
        #pragma unroll
        for (int mi = 0; mi < 4; mi++) {
            int rr = row0 + ty * 4 + mi;
            float4 xq = *(const float4*)(x_node + (rr / 3) * 4);
            xr[mi][0] = xq.x; xr[mi][1] = xq.y; xr[mi][2] = xq.z; xr[mi][3] = xq.w;
        }
        __syncthreads();

        {
            ull acc[4][2];
            #pragma unroll
            for (int mi = 0; mi < 4; mi++) { acc[mi][0] = 0ull; acc[mi][1] = 0ull; }
            const float* bB = sB2 + 4 * tx;
            const float* v1B = v1s + ty * 4 * 36;
            #pragma unroll 1
            for (int a = 0; a < 4; a++) {
                const float* bA = bB + a * 32 * 36;
                #pragma unroll 4
                for (int c = 0; c < 32; c++) {
                    ull b0 = lds64(bA + c * 36);
                    ull b1 = lds64(bA + c * 36 + 2);
                    #pragma unroll
                    for (int mi = 0; mi < 4; mi++) {
                        float sv = v1B[mi * 36 + c];
                        ull ad = dup2(xr[mi][a] * sv);
                        acc[mi][0] = fma2(b0, ad, acc[mi][0]);
                        acc[mi][1] = fma2(b1, ad, acc[mi][1]);
                    }
                }
            }
            #pragma unroll
            for (int mi = 0; mi < 4; mi++) {
                int row = row0 + ty * 4 + mi;
                float vv[4];
                unpack2(acc[mi][0], vv[0], vv[1]);
                unpack2(acc[mi][1], vv[2], vv[3]);
                int n = row / 3, ii = row - 3 * n;
                #pragma unroll
                for (int j = 0; j < 4; j++) {
                    int c = 4 * tx + j;
                    outV[(long)n * 96 + c * 3 + ii] =
                        vv[j] + g_skip_v[(long)n * 96 + c * 3 + ii];
                }
            }
        }
    }
}

// ---------------- launch ----------------
extern "C" void kernel_launch(void* const* d_in, const int* in_sizes, int n_in,
                              void* d_out, int out_size) {
    const float* s_in     = (const float*)d_in[0];
    const float* v_in     = (const float*)d_in[1];
    const float* x_node   = (const float*)d_in[2];
    const float* radial   = (const float*)d_in[3];
    const float* Y0       = (const float*)d_in[4];
    const float* Y1       = (const float*)d_in[5];
    const int*   species  = (const int*)d_in[6];
    const int*   senders  = (const int*)d_in[7];
    const int*   receivers= (const int*)d_in[8];
    const float* Wskip0   = (const float*)d_in[9];
    const float* Wskip1   = (const float*)d_in[10];
    const float* Wu0      = (const float*)d_in[11];
    const float* Wu1      = (const float*)d_in[12];
    const float* Wm1      = (const float*)d_in[13];
    const float* Wm2      = (const float*)d_in[14];
    const float* Wm3      = (const float*)d_in[15];
    const float* Wd0      = (const float*)d_in[16];
    const float* Wd1      = (const float*)d_in[17];
    const float* Wt0      = (const float*)d_in[18];
    const float* Wt1      = (const float*)d_in[19];
    const float* Wq       = (const float*)d_in[20];
    const float* wqml     = (const float*)d_in[21];
    const float* Wo       = (const float*)d_in[22];
    const float* bo       = (const float*)d_in[23];

    float* out0 = (float*)d_out;
    float* outS = out0 + Nn;
    float* outV = outS + Nn * C0;

    static bool attr_done = false;
    size_t smem_pre  = (4096 + 1024 + 16384 + 4096 + 8 * 160) * sizeof(float);
    size_t smem_edge = (512 + 4096 + 18432 + EW * 1568) * sizeof(float);
    size_t smem_node = NODE_SMEM_FLOATS * sizeof(float);   // ~106.8 KB -> 2 blocks/SM
    if (!attr_done) {
        cudaFuncSetAttribute(node_pre_kernel, cudaFuncAttributeMaxDynamicSharedMemorySize, (int)smem_pre);
        cudaFuncSetAttribute(edge_kernel,     cudaFuncAttributeMaxDynamicSharedMemorySize, (int)smem_edge);
        cudaFuncSetAttribute(node_kernel,     cudaFuncAttributeMaxDynamicSharedMemorySize, (int)smem_node);
        attr_done = true;
    }

    node_pre_kernel<<<296, 256, smem_pre>>>(s_in, v_in, species, Wskip0, Wskip1, Wu0, Wu1);
    edge_kernel<<<148, 32 * EW, smem_edge>>>(radial, Y0, Y1, senders, receivers, Wm1, Wm2, Wm3);
    node_kernel<<<320, 256, smem_node>>>(Wd0, Wd1, Wt0, Wt1, x_node, Wq, wqml, Wo, bo,
                                         out0, outS, outV);
}